// round 4
// baseline (speedup 1.0000x reference)
#include <cuda_runtime.h>

#define NN 50000
#define NE 800000
#define ET (NE + NN)
#define CIN 256
#define C1 256
#define C2 128
#define NG 100
#define NH 4
#define NEG_SLOPE 0.2f
#define SM_EPS 1e-16f

// ---------------- scratch (static device arrays; no allocation) ----------------
__device__ float    g_h1[NN * C1];      // layer1 pre-aggregation features
__device__ float    g_out1[NN * C1];    // layer1 aggregated output
__device__ float    g_h2[NN * C2];      // layer2 pre-aggregation features
__device__ float    g_out2[NN * C2];    // layer2 aggregated output
__device__ float    g_asrc1[NN * NH], g_adst1[NN * NH];
__device__ float    g_asrc2[NN],      g_adst2[NN];
__device__ unsigned g_amax1[NN * NH];
__device__ unsigned g_amax2[NN];
__device__ float    g_den1[NN * NH],  g_den2[NN];
__device__ float    g_ealpha[ET * NH]; // per-edge alpha, then exp values
__device__ int      g_cnt[NG];
__device__ int      g_src[ET], g_dst[ET];   // decoded edge endpoints (int32)
__device__ int      g_batch32[NN];          // decoded batch ids (int32)
__device__ int      g_e_is64, g_b_is64;     // dtype probe results

// monotone float<->uint encoding for atomicMax over signed floats
__device__ __forceinline__ unsigned fenc(float f) {
    unsigned b = __float_as_uint(f);
    return (b & 0x80000000u) ? ~b : (b | 0x80000000u);
}
__device__ __forceinline__ float fdec(unsigned k) {
    unsigned b = (k & 0x80000000u) ? (k & 0x7FFFFFFFu) : ~k;
    return __uint_as_float(b);
}

// ---------------- dtype probe + index conversion ----------------
// Edge probe: src values are random in [0,NN); if the buffer is int32, an
// int64 read packs two values -> >= 2^32 almost surely -> detected.
// Batch probe: batch is SORTED, so the head can be all-zero either way.
// Probe BOTH head and tail (indices [NN/2-256, NN/2) under the int64 view):
//  - truly int64: indices < NN, values in [0,NG) -> passes
//  - truly int32: tail int64 reads pack two values ~99 -> >= 2^32 -> fails
__global__ void probe_kernel(const void* __restrict__ ei,
                             const void* __restrict__ batch) {
    if (threadIdx.x != 0 || blockIdx.x != 0) return;
    const long long* e64 = (const long long*)ei;
    int ok = 1;
    for (int i = 0; i < 256; i++) {
        long long v = e64[i];
        if (v < 0 || v >= NN) { ok = 0; break; }
    }
    g_e_is64 = ok;
    const long long* b64 = (const long long*)batch;
    int okb = 1;
    for (int i = 0; i < 256 && okb; i++) {
        long long v = b64[i];
        if (v < 0 || v >= NG) okb = 0;
    }
    for (int i = NN / 2 - 256; i < NN / 2 && okb; i++) {
        long long v = b64[i];
        if (v < 0 || v >= NG) okb = 0;
    }
    g_b_is64 = okb;
}

__global__ void convert_kernel(const void* __restrict__ ei,
                               const void* __restrict__ batch) {
    int i = blockIdx.x * blockDim.x + threadIdx.x;
    if (i < ET) {
        int s, d;
        if (i < NE) {
            if (g_e_is64) {
                const long long* p = (const long long*)ei;
                s = (int)p[i]; d = (int)p[NE + i];
            } else {
                const int* p = (const int*)ei;
                s = p[i]; d = p[NE + i];
            }
        } else {
            s = i - NE; d = s;  // appended self-loops
        }
        // defensive clamp (no-op when probe is right)
        s = min(max(s, 0), NN - 1);
        d = min(max(d, 0), NN - 1);
        g_src[i] = s; g_dst[i] = d;
    }
    if (i < NN) {
        int b;
        if (g_b_is64) b = (int)((const long long*)batch)[i];
        else          b = ((const int*)batch)[i];
        g_batch32[i] = min(max(b, 0), NG - 1);
    }
}

// ---------------- zero / init kernels ----------------
__global__ void zero1_kernel() {
    int i = blockIdx.x * blockDim.x + threadIdx.x;
    if (i < NN * C1) g_out1[i] = 0.f;
    if (i < NN * NH) { g_amax1[i] = 0u; g_den1[i] = 0.f; }
}
__global__ void zero2_kernel(float* __restrict__ out) {
    int i = blockIdx.x * blockDim.x + threadIdx.x;
    if (i < NN * C2) g_out2[i] = 0.f;
    if (i < NN)      { g_amax2[i] = 0u; g_den2[i] = 0.f; }
    if (i < NG * C2) out[i] = 0.f;
    if (i < NG)      g_cnt[i] = 0;
}

// ---------------- SGEMM: C[M,N] = A[M,K=256] * B[K,N]  (optionally A := relu(A+bias)) ----
template <int LAYER>
__global__ void __launch_bounds__(256, 2)
gemm_kernel(const float* __restrict__ Ain,
            const float* __restrict__ B,
            const float* __restrict__ bias) {
    constexpr int K = 256;
    constexpr int N = (LAYER == 1) ? C1 : C2;
    constexpr bool FUSE = (LAYER == 2);
    const float* A = (LAYER == 1) ? Ain : g_out1;
    float*       C = (LAYER == 1) ? g_h1 : g_h2;
    const int M = NN;

    __shared__ float As[8][128];
    __shared__ float Bs[8][128];

    int tid = threadIdx.x;
    int m0 = blockIdx.y * 128;
    int n0 = blockIdx.x * 128;
    int ty = tid >> 4, tx = tid & 15;
    int arow = tid >> 1;
    int acol = (tid & 1) * 4;
    int brow = tid >> 5;
    int bcol = (tid & 31) * 4;

    float acc[8][8];
#pragma unroll
    for (int i = 0; i < 8; i++)
#pragma unroll
        for (int j = 0; j < 8; j++) acc[i][j] = 0.f;

    int gr = m0 + arow;
    const float* Arow = A + (size_t)gr * K;

    for (int k0 = 0; k0 < K; k0 += 8) {
        float4 av = make_float4(0.f, 0.f, 0.f, 0.f);
        if (gr < M) av = *(const float4*)(Arow + k0 + acol);
        if (FUSE) {
            av.x = fmaxf(av.x + bias[k0 + acol + 0], 0.f);
            av.y = fmaxf(av.y + bias[k0 + acol + 1], 0.f);
            av.z = fmaxf(av.z + bias[k0 + acol + 2], 0.f);
            av.w = fmaxf(av.w + bias[k0 + acol + 3], 0.f);
        }
        As[acol + 0][arow] = av.x;
        As[acol + 1][arow] = av.y;
        As[acol + 2][arow] = av.z;
        As[acol + 3][arow] = av.w;
        *(float4*)&Bs[brow][bcol] =
            *(const float4*)(B + (size_t)(k0 + brow) * N + n0 + bcol);
        __syncthreads();
#pragma unroll
        for (int k = 0; k < 8; k++) {
            float a[8], b[8];
            *(float4*)(a)     = *(float4*)&As[k][ty * 8];
            *(float4*)(a + 4) = *(float4*)&As[k][ty * 8 + 4];
            *(float4*)(b)     = *(float4*)&Bs[k][tx * 8];
            *(float4*)(b + 4) = *(float4*)&Bs[k][tx * 8 + 4];
#pragma unroll
            for (int i = 0; i < 8; i++)
#pragma unroll
                for (int j = 0; j < 8; j++) acc[i][j] += a[i] * b[j];
        }
        __syncthreads();
    }

#pragma unroll
    for (int i = 0; i < 8; i++) {
        int r = m0 + ty * 8 + i;
        if (r < M) {
            *(float4*)(C + (size_t)r * N + n0 + tx * 8) =
                make_float4(acc[i][0], acc[i][1], acc[i][2], acc[i][3]);
            *(float4*)(C + (size_t)r * N + n0 + tx * 8 + 4) =
                make_float4(acc[i][4], acc[i][5], acc[i][6], acc[i][7]);
        }
    }
}

// ---------------- attention dot products ----------------
__global__ void dots1_kernel(const float* __restrict__ att_src,
                             const float* __restrict__ att_dst) {
    int n = blockIdx.x;
    int c = threadIdx.x;  // 256 threads
    float v = g_h1[n * C1 + c];
    float s = v * att_src[c];
    float d = v * att_dst[c];
#pragma unroll
    for (int o = 16; o > 0; o >>= 1) {
        s += __shfl_xor_sync(0xFFFFFFFFu, s, o);
        d += __shfl_xor_sync(0xFFFFFFFFu, d, o);
    }
    __shared__ float ss[8], sd[8];
    int w = c >> 5;
    if ((c & 31) == 0) { ss[w] = s; sd[w] = d; }
    __syncthreads();
    if (c < NH) {
        g_asrc1[n * NH + c] = ss[2 * c] + ss[2 * c + 1];
        g_adst1[n * NH + c] = sd[2 * c] + sd[2 * c + 1];
    }
}

__global__ void dots2_kernel(const float* __restrict__ att_src,
                             const float* __restrict__ att_dst) {
    int n = blockIdx.x;
    int c = threadIdx.x;  // 128 threads
    float v = g_h2[n * C2 + c];
    float s = v * att_src[c];
    float d = v * att_dst[c];
#pragma unroll
    for (int o = 16; o > 0; o >>= 1) {
        s += __shfl_xor_sync(0xFFFFFFFFu, s, o);
        d += __shfl_xor_sync(0xFFFFFFFFu, d, o);
    }
    __shared__ float ss[4], sd[4];
    if ((c & 31) == 0) { ss[c >> 5] = s; sd[c >> 5] = d; }
    __syncthreads();
    if (c == 0) {
        g_asrc2[n] = ss[0] + ss[1] + ss[2] + ss[3];
        g_adst2[n] = sd[0] + sd[1] + sd[2] + sd[3];
    }
}

// ---------------- edge pass 1: alpha = leaky(asrc[s]+adst[d]); segment max ----
__global__ void e1_l1() {
    int e = blockIdx.x * blockDim.x + threadIdx.x;
    if (e >= ET) return;
    int s = g_src[e], d = g_dst[e];
    float4 as = *(const float4*)(g_asrc1 + s * 4);
    float4 ad = *(const float4*)(g_adst1 + d * 4);
    float al[4] = {as.x + ad.x, as.y + ad.y, as.z + ad.z, as.w + ad.w};
#pragma unroll
    for (int h = 0; h < 4; h++) {
        al[h] = (al[h] > 0.f) ? al[h] : NEG_SLOPE * al[h];
        atomicMax(&g_amax1[d * 4 + h], fenc(al[h]));
    }
    *(float4*)(g_ealpha + (size_t)e * 4) = make_float4(al[0], al[1], al[2], al[3]);
}

__global__ void e1_l2() {
    int e = blockIdx.x * blockDim.x + threadIdx.x;
    if (e >= ET) return;
    int s = g_src[e], d = g_dst[e];
    float al = g_asrc2[s] + g_adst2[d];
    al = (al > 0.f) ? al : NEG_SLOPE * al;
    atomicMax(&g_amax2[d], fenc(al));
    g_ealpha[e] = al;
}

// ---------------- edge pass 2: exp + segment sum ----------------
__global__ void e2_l1() {
    int e = blockIdx.x * blockDim.x + threadIdx.x;
    if (e >= ET) return;
    int d = g_dst[e];
    float4 al = *(const float4*)(g_ealpha + (size_t)e * 4);
    float ex[4];
    ex[0] = expf(al.x - fdec(g_amax1[d * 4 + 0]));
    ex[1] = expf(al.y - fdec(g_amax1[d * 4 + 1]));
    ex[2] = expf(al.z - fdec(g_amax1[d * 4 + 2]));
    ex[3] = expf(al.w - fdec(g_amax1[d * 4 + 3]));
#pragma unroll
    for (int h = 0; h < 4; h++) atomicAdd(&g_den1[d * 4 + h], ex[h]);
    *(float4*)(g_ealpha + (size_t)e * 4) = make_float4(ex[0], ex[1], ex[2], ex[3]);
}

__global__ void e2_l2() {
    int e = blockIdx.x * blockDim.x + threadIdx.x;
    if (e >= ET) return;
    int d = g_dst[e];
    float ex = expf(g_ealpha[e] - fdec(g_amax2[d]));
    atomicAdd(&g_den2[d], ex);
    g_ealpha[e] = ex;
}

// ---------------- edge pass 3: weighted gather/scatter aggregate ----------------
__global__ void e3_l1() {
    int gtid = blockIdx.x * blockDim.x + threadIdx.x;
    int e = gtid >> 5;
    int lane = threadIdx.x & 31;
    if (e >= ET) return;
    int s = g_src[e], d = g_dst[e];
    float wv = 0.f;
    if (lane < 4) wv = g_ealpha[(size_t)e * 4 + lane] / (g_den1[d * 4 + lane] + SM_EPS);
    float w[4];
#pragma unroll
    for (int h = 0; h < 4; h++) w[h] = __shfl_sync(0xFFFFFFFFu, wv, h);
    const float* hr = g_h1 + (size_t)s * C1;
    float* orow = g_out1 + (size_t)d * C1;
#pragma unroll
    for (int j = 0; j < 8; j++) {
        int c = j * 32 + lane;
        atomicAdd(orow + c, hr[c] * w[j >> 1]);
    }
}

__global__ void e3_l2() {
    int gtid = blockIdx.x * blockDim.x + threadIdx.x;
    int e = gtid >> 5;
    int lane = threadIdx.x & 31;
    if (e >= ET) return;
    int s = g_src[e], d = g_dst[e];
    float w = 0.f;
    if (lane == 0) w = g_ealpha[e] / (g_den2[d] + SM_EPS);
    w = __shfl_sync(0xFFFFFFFFu, w, 0);
    const float* hr = g_h2 + (size_t)s * C2;
    float* orow = g_out2 + (size_t)d * C2;
#pragma unroll
    for (int j = 0; j < 4; j++) {
        int c = j * 32 + lane;
        atomicAdd(orow + c, hr[c] * w);
    }
}

// ---------------- pooling ----------------
__global__ void count_kernel() {
    int n = blockIdx.x * blockDim.x + threadIdx.x;
    if (n < NN) atomicAdd(&g_cnt[g_batch32[n]], 1);
}

__global__ void pool_kernel(const float* __restrict__ bias2,
                            float* __restrict__ out) {
    int i = blockIdx.x * blockDim.x + threadIdx.x;
    if (i >= NN * C2) return;
    int n = i >> 7, c = i & 127;
    float v = fmaxf(g_out2[i] + bias2[c], 0.f);
    atomicAdd(out + g_batch32[n] * C2 + c, v);
}

__global__ void final_kernel(float* __restrict__ out) {
    int i = blockIdx.x * blockDim.x + threadIdx.x;
    if (i < NG * C2) out[i] /= fmaxf((float)g_cnt[i >> 7], 1.f);
}

// ---------------- host launcher ----------------
extern "C" void kernel_launch(void* const* d_in, const int* in_sizes, int n_in,
                              void* d_out, int out_size) {
    // Resolve inputs robustly: unique sizes by value, equal-sized triples in order.
    const void *x = 0, *W1 = 0, *W2 = 0, *ei = 0, *batch = 0;
    const void *t256[3] = {0, 0, 0};  // att_src1, att_dst1, bias1
    const void *t128[3] = {0, 0, 0};  // att_src2, att_dst2, bias2
    int n256 = 0, n128 = 0;
    for (int i = 0; i < n_in; i++) {
        int sz = in_sizes[i];
        if      (sz == NN * CIN)  x = d_in[i];
        else if (sz == CIN * C1)  W1 = d_in[i];
        else if (sz == C1 * C2)   W2 = d_in[i];
        else if (sz == 2 * NE)    ei = d_in[i];
        else if (sz == NN)        batch = d_in[i];
        else if (sz == 256 && n256 < 3) t256[n256++] = d_in[i];
        else if (sz == 128 && n128 < 3) t128[n128++] = d_in[i];
    }
    const float* as1 = (const float*)t256[0];
    const float* ad1 = (const float*)t256[1];
    const float* b1  = (const float*)t256[2];
    const float* as2 = (const float*)t128[0];
    const float* ad2 = (const float*)t128[1];
    const float* b2  = (const float*)t128[2];
    float* out = (float*)d_out;

    probe_kernel<<<1, 32>>>(ei, batch);
    convert_kernel<<<(ET + 255) / 256, 256>>>(ei, batch);
    zero1_kernel<<<(NN * C1 + 255) / 256, 256>>>();
    zero2_kernel<<<(NN * C2 + 255) / 256, 256>>>(out);

    // layer 1
    gemm_kernel<1><<<dim3(C1 / 128, (NN + 127) / 128), 256>>>((const float*)x, (const float*)W1, nullptr);
    dots1_kernel<<<NN, 256>>>(as1, ad1);
    e1_l1<<<(ET + 255) / 256, 256>>>();
    e2_l1<<<(ET + 255) / 256, 256>>>();
    e3_l1<<<(ET * 32 + 255) / 256, 256>>>();

    // layer 2 (relu(out1 + b1) fused into GEMM2 A-load)
    gemm_kernel<2><<<dim3(C2 / 128, (NN + 127) / 128), 256>>>(nullptr, (const float*)W2, b1);
    dots2_kernel<<<NN, 128>>>(as2, ad2);
    e1_l2<<<(ET + 255) / 256, 256>>>();
    e2_l2<<<(ET + 255) / 256, 256>>>();
    e3_l2<<<(ET * 32 + 255) / 256, 256>>>();

    // mean pool
    count_kernel<<<(NN + 255) / 256, 256>>>();
    pool_kernel<<<(NN * C2 + 255) / 256, 256>>>(b2, out);
    final_kernel<<<(NG * C2 + 255) / 256, 256>>>(out);
}

// round 5
// speedup vs baseline: 1.5959x; 1.5959x over previous
#include <cuda_runtime.h>
#include <math_constants.h>

#define NN 50000
#define NE 800000
#define ET (NE + NN)
#define CIN 256
#define C1 256
#define C2 128
#define NG 100
#define NH 4
#define NEG_SLOPE 0.2f
#define SM_EPS 1e-16f
#define CAP 128   // per-warp alpha cache (avg degree ~17; recompute fallback beyond)

// ---------------- scratch (static device arrays; no allocation) ----------------
__device__ float g_h1[NN * C1];      // layer1 pre-aggregation features
__device__ float g_out1[NN * C1];    // layer1 aggregated output
__device__ float g_h2[NN * C2];      // layer2 pre-aggregation features
__device__ float g_out2[NN * C2];    // layer2 aggregated output
__device__ float g_asrc1[NN * NH], g_adst1[NN * NH];
__device__ float g_asrc2[NN],      g_adst2[NN];
__device__ int   g_cnt[NG];
__device__ int   g_src[ET], g_dst[ET];   // decoded edge endpoints (int32)
__device__ int   g_batch32[NN];          // decoded batch ids (int32)
__device__ int   g_e_is64, g_b_is64;     // dtype probe results
__device__ int   g_deg[NN];              // dst histogram
__device__ int   g_pos[NN];              // scatter cursors
__device__ int   g_off[NN + 1];          // CSR offsets (by dst)
__device__ int   g_csr_src[ET];          // src node per CSR slot

// ---------------- dtype probe + index conversion ----------------
// Edge probe: values random in [0,NN); int32 data read as int64 packs two
// values -> >= 2^32 -> detected. Batch is SORTED so also probe the tail
// (head can be all-zero under either dtype).
__global__ void probe_kernel(const void* __restrict__ ei,
                             const void* __restrict__ batch) {
    if (threadIdx.x != 0 || blockIdx.x != 0) return;
    const long long* e64 = (const long long*)ei;
    int ok = 1;
    for (int i = 0; i < 256; i++) {
        long long v = e64[i];
        if (v < 0 || v >= NN) { ok = 0; break; }
    }
    g_e_is64 = ok;
    const long long* b64 = (const long long*)batch;
    int okb = 1;
    for (int i = 0; i < 256 && okb; i++) {
        long long v = b64[i];
        if (v < 0 || v >= NG) okb = 0;
    }
    for (int i = NN / 2 - 256; i < NN / 2 && okb; i++) {
        long long v = b64[i];
        if (v < 0 || v >= NG) okb = 0;
    }
    g_b_is64 = okb;
}

// decode indices, zero small scratch, count graph sizes
__global__ void convert_kernel(const void* __restrict__ ei,
                               const void* __restrict__ batch,
                               float* __restrict__ out) {
    int i = blockIdx.x * blockDim.x + threadIdx.x;
    if (i < ET) {
        int s, d;
        if (i < NE) {
            if (g_e_is64) {
                const long long* p = (const long long*)ei;
                s = (int)p[i]; d = (int)p[NE + i];
            } else {
                const int* p = (const int*)ei;
                s = p[i]; d = p[NE + i];
            }
        } else {
            s = i - NE; d = s;  // appended self-loops
        }
        s = min(max(s, 0), NN - 1);
        d = min(max(d, 0), NN - 1);
        g_src[i] = s; g_dst[i] = d;
    }
    if (i < NN) {
        int b;
        if (g_b_is64) b = (int)((const long long*)batch)[i];
        else          b = ((const int*)batch)[i];
        b = min(max(b, 0), NG - 1);
        g_batch32[i] = b;
        g_deg[i] = 0; g_pos[i] = 0;
        atomicAdd(&g_cnt[b], 1);  // g_cnt zeroed below by thread block 0 range
    }
    if (i < NG * C2) out[i] = 0.f;
}
// g_cnt must be zero BEFORE convert's atomicAdd -> separate tiny kernel first.
__global__ void zcnt_kernel() {
    int i = threadIdx.x;
    if (i < NG) g_cnt[i] = 0;
}

// ---------------- CSR build ----------------
__global__ void hist_kernel() {
    int e = blockIdx.x * blockDim.x + threadIdx.x;
    if (e < ET) atomicAdd(&g_deg[g_dst[e]], 1);
}

// single-CTA exclusive scan of g_deg -> g_off (50k elements)
__global__ void scan_kernel() {
    __shared__ int psum[1024];
    const int CH = (NN + 1023) / 1024;
    int t = threadIdx.x;
    int b = t * CH;
    int sum = 0;
    for (int k = 0; k < CH; k++) {
        int idx = b + k;
        if (idx < NN) sum += g_deg[idx];
    }
    psum[t] = sum;
    __syncthreads();
    for (int off = 1; off < 1024; off <<= 1) {
        int v = (t >= off) ? psum[t - off] : 0;
        __syncthreads();
        psum[t] += v;
        __syncthreads();
    }
    int run = (t > 0) ? psum[t - 1] : 0;
    for (int k = 0; k < CH; k++) {
        int idx = b + k;
        if (idx < NN) { g_off[idx] = run; run += g_deg[idx]; }
    }
    if (t == 1023) g_off[NN] = run;
}

__global__ void scatter_kernel() {
    int e = blockIdx.x * blockDim.x + threadIdx.x;
    if (e >= ET) return;
    int d = g_dst[e];
    int slot = g_off[d] + atomicAdd(&g_pos[d], 1);
    g_csr_src[slot] = g_src[e];
}

// ---------------- SGEMM: C[M,N] = A[M,K=256] * B[K,N]  (optionally A := relu(A+bias)) ----
template <int LAYER>
__global__ void __launch_bounds__(256, 2)
gemm_kernel(const float* __restrict__ Ain,
            const float* __restrict__ B,
            const float* __restrict__ bias) {
    constexpr int K = 256;
    constexpr int N = (LAYER == 1) ? C1 : C2;
    constexpr bool FUSE = (LAYER == 2);
    const float* A = (LAYER == 1) ? Ain : g_out1;
    float*       C = (LAYER == 1) ? g_h1 : g_h2;
    const int M = NN;

    __shared__ float As[8][128];
    __shared__ float Bs[8][128];

    int tid = threadIdx.x;
    int m0 = blockIdx.y * 128;
    int n0 = blockIdx.x * 128;
    int ty = tid >> 4, tx = tid & 15;
    int arow = tid >> 1;
    int acol = (tid & 1) * 4;
    int brow = tid >> 5;
    int bcol = (tid & 31) * 4;

    float acc[8][8];
#pragma unroll
    for (int i = 0; i < 8; i++)
#pragma unroll
        for (int j = 0; j < 8; j++) acc[i][j] = 0.f;

    int gr = m0 + arow;
    const float* Arow = A + (size_t)gr * K;

    for (int k0 = 0; k0 < K; k0 += 8) {
        float4 av = make_float4(0.f, 0.f, 0.f, 0.f);
        if (gr < M) av = *(const float4*)(Arow + k0 + acol);
        if (FUSE) {
            av.x = fmaxf(av.x + bias[k0 + acol + 0], 0.f);
            av.y = fmaxf(av.y + bias[k0 + acol + 1], 0.f);
            av.z = fmaxf(av.z + bias[k0 + acol + 2], 0.f);
            av.w = fmaxf(av.w + bias[k0 + acol + 3], 0.f);
        }
        As[acol + 0][arow] = av.x;
        As[acol + 1][arow] = av.y;
        As[acol + 2][arow] = av.z;
        As[acol + 3][arow] = av.w;
        *(float4*)&Bs[brow][bcol] =
            *(const float4*)(B + (size_t)(k0 + brow) * N + n0 + bcol);
        __syncthreads();
#pragma unroll
        for (int k = 0; k < 8; k++) {
            float a[8], b[8];
            *(float4*)(a)     = *(float4*)&As[k][ty * 8];
            *(float4*)(a + 4) = *(float4*)&As[k][ty * 8 + 4];
            *(float4*)(b)     = *(float4*)&Bs[k][tx * 8];
            *(float4*)(b + 4) = *(float4*)&Bs[k][tx * 8 + 4];
#pragma unroll
            for (int i = 0; i < 8; i++)
#pragma unroll
                for (int j = 0; j < 8; j++) acc[i][j] += a[i] * b[j];
        }
        __syncthreads();
    }

#pragma unroll
    for (int i = 0; i < 8; i++) {
        int r = m0 + ty * 8 + i;
        if (r < M) {
            *(float4*)(C + (size_t)r * N + n0 + tx * 8) =
                make_float4(acc[i][0], acc[i][1], acc[i][2], acc[i][3]);
            *(float4*)(C + (size_t)r * N + n0 + tx * 8 + 4) =
                make_float4(acc[i][4], acc[i][5], acc[i][6], acc[i][7]);
        }
    }
}

// ---------------- attention dot products ----------------
__global__ void dots1_kernel(const float* __restrict__ att_src,
                             const float* __restrict__ att_dst) {
    int n = blockIdx.x;
    int c = threadIdx.x;  // 256 threads
    float v = g_h1[n * C1 + c];
    float s = v * att_src[c];
    float d = v * att_dst[c];
#pragma unroll
    for (int o = 16; o > 0; o >>= 1) {
        s += __shfl_xor_sync(0xFFFFFFFFu, s, o);
        d += __shfl_xor_sync(0xFFFFFFFFu, d, o);
    }
    __shared__ float ss[8], sd[8];
    int w = c >> 5;
    if ((c & 31) == 0) { ss[w] = s; sd[w] = d; }
    __syncthreads();
    if (c < NH) {
        g_asrc1[n * NH + c] = ss[2 * c] + ss[2 * c + 1];
        g_adst1[n * NH + c] = sd[2 * c] + sd[2 * c + 1];
    }
}

__global__ void dots2_kernel(const float* __restrict__ att_src,
                             const float* __restrict__ att_dst) {
    int n = blockIdx.x;
    int c = threadIdx.x;  // 128 threads
    float v = g_h2[n * C2 + c];
    float s = v * att_src[c];
    float d = v * att_dst[c];
#pragma unroll
    for (int o = 16; o > 0; o >>= 1) {
        s += __shfl_xor_sync(0xFFFFFFFFu, s, o);
        d += __shfl_xor_sync(0xFFFFFFFFu, d, o);
    }
    __shared__ float ss[4], sd[4];
    if ((c & 31) == 0) { ss[c >> 5] = s; sd[c >> 5] = d; }
    __syncthreads();
    if (c == 0) {
        g_asrc2[n] = ss[0] + ss[1] + ss[2] + ss[3];
        g_adst2[n] = sd[0] + sd[1] + sd[2] + sd[3];
    }
}

// ---------------- fused attention + aggregation (one warp per dst node) ----------------
__device__ __forceinline__ float lrelu(float a) {
    return (a > 0.f) ? a : NEG_SLOPE * a;
}

__global__ void __launch_bounds__(256) agg1_kernel() {
    __shared__ float cache[8][NH * CAP];  // [head][edge] per warp: 16KB
    int wid = threadIdx.x >> 5, lane = threadIdx.x & 31;
    int n = blockIdx.x * 8 + wid;
    if (n >= NN) return;
    float* ch = cache[wid];
    int beg = g_off[n], end = g_off[n + 1];
    int deg = end - beg;
    float4 ad = *(const float4*)(g_adst1 + n * 4);

    // pass A: alpha per edge (cached), per-head max
    float mx0 = -CUDART_INF_F, mx1 = -CUDART_INF_F, mx2 = -CUDART_INF_F, mx3 = -CUDART_INF_F;
    for (int i = lane; i < deg; i += 32) {
        int s = g_csr_src[beg + i];
        float4 as = *(const float4*)(g_asrc1 + s * 4);
        float a0 = lrelu(as.x + ad.x), a1 = lrelu(as.y + ad.y);
        float a2 = lrelu(as.z + ad.z), a3 = lrelu(as.w + ad.w);
        if (i < CAP) {
            ch[0 * CAP + i] = a0; ch[1 * CAP + i] = a1;
            ch[2 * CAP + i] = a2; ch[3 * CAP + i] = a3;
        }
        mx0 = fmaxf(mx0, a0); mx1 = fmaxf(mx1, a1);
        mx2 = fmaxf(mx2, a2); mx3 = fmaxf(mx3, a3);
    }
#pragma unroll
    for (int o = 16; o > 0; o >>= 1) {
        mx0 = fmaxf(mx0, __shfl_xor_sync(0xFFFFFFFFu, mx0, o));
        mx1 = fmaxf(mx1, __shfl_xor_sync(0xFFFFFFFFu, mx1, o));
        mx2 = fmaxf(mx2, __shfl_xor_sync(0xFFFFFFFFu, mx2, o));
        mx3 = fmaxf(mx3, __shfl_xor_sync(0xFFFFFFFFu, mx3, o));
    }
    __syncwarp();

    // pass B: exp (cached in place), per-head sum
    float d0 = 0.f, d1 = 0.f, d2 = 0.f, d3 = 0.f;
    for (int i = lane; i < deg; i += 32) {
        float a0, a1, a2, a3;
        if (i < CAP) {
            a0 = ch[0 * CAP + i]; a1 = ch[1 * CAP + i];
            a2 = ch[2 * CAP + i]; a3 = ch[3 * CAP + i];
        } else {
            int s = g_csr_src[beg + i];
            float4 as = *(const float4*)(g_asrc1 + s * 4);
            a0 = lrelu(as.x + ad.x); a1 = lrelu(as.y + ad.y);
            a2 = lrelu(as.z + ad.z); a3 = lrelu(as.w + ad.w);
        }
        float e0 = expf(a0 - mx0), e1 = expf(a1 - mx1);
        float e2 = expf(a2 - mx2), e3 = expf(a3 - mx3);
        if (i < CAP) {
            ch[0 * CAP + i] = e0; ch[1 * CAP + i] = e1;
            ch[2 * CAP + i] = e2; ch[3 * CAP + i] = e3;
        }
        d0 += e0; d1 += e1; d2 += e2; d3 += e3;
    }
#pragma unroll
    for (int o = 16; o > 0; o >>= 1) {
        d0 += __shfl_xor_sync(0xFFFFFFFFu, d0, o);
        d1 += __shfl_xor_sync(0xFFFFFFFFu, d1, o);
        d2 += __shfl_xor_sync(0xFFFFFFFFu, d2, o);
        d3 += __shfl_xor_sync(0xFFFFFFFFu, d3, o);
    }
    float r0 = 1.f / (d0 + SM_EPS), r1 = 1.f / (d1 + SM_EPS);
    float r2 = 1.f / (d2 + SM_EPS), r3 = 1.f / (d3 + SM_EPS);
    __syncwarp();

    // pass C: weighted gather-accumulate; lane owns channels j*32+lane
    float acc[8];
#pragma unroll
    for (int j = 0; j < 8; j++) acc[j] = 0.f;
    for (int i = 0; i < deg; i++) {
        float w0, w1, w2, w3;
        if (i < CAP) {
            w0 = ch[0 * CAP + i] * r0; w1 = ch[1 * CAP + i] * r1;
            w2 = ch[2 * CAP + i] * r2; w3 = ch[3 * CAP + i] * r3;
        } else {
            int s = g_csr_src[beg + i];
            float4 as = *(const float4*)(g_asrc1 + s * 4);
            w0 = expf(lrelu(as.x + ad.x) - mx0) * r0;
            w1 = expf(lrelu(as.y + ad.y) - mx1) * r1;
            w2 = expf(lrelu(as.z + ad.z) - mx2) * r2;
            w3 = expf(lrelu(as.w + ad.w) - mx3) * r3;
        }
        int s = g_csr_src[beg + i];
        const float* hr = g_h1 + (size_t)s * C1;
        acc[0] += hr[0 * 32 + lane] * w0;
        acc[1] += hr[1 * 32 + lane] * w0;
        acc[2] += hr[2 * 32 + lane] * w1;
        acc[3] += hr[3 * 32 + lane] * w1;
        acc[4] += hr[4 * 32 + lane] * w2;
        acc[5] += hr[5 * 32 + lane] * w2;
        acc[6] += hr[6 * 32 + lane] * w3;
        acc[7] += hr[7 * 32 + lane] * w3;
    }
    float* orow = g_out1 + (size_t)n * C1;
#pragma unroll
    for (int j = 0; j < 8; j++) orow[j * 32 + lane] = acc[j];
}

__global__ void __launch_bounds__(256) agg2_kernel() {
    __shared__ float cache[8][CAP];  // 4KB
    int wid = threadIdx.x >> 5, lane = threadIdx.x & 31;
    int n = blockIdx.x * 8 + wid;
    if (n >= NN) return;
    float* ch = cache[wid];
    int beg = g_off[n], end = g_off[n + 1];
    int deg = end - beg;
    float ad = g_adst2[n];

    float mx = -CUDART_INF_F;
    for (int i = lane; i < deg; i += 32) {
        float a = lrelu(g_asrc2[g_csr_src[beg + i]] + ad);
        if (i < CAP) ch[i] = a;
        mx = fmaxf(mx, a);
    }
#pragma unroll
    for (int o = 16; o > 0; o >>= 1)
        mx = fmaxf(mx, __shfl_xor_sync(0xFFFFFFFFu, mx, o));
    __syncwarp();

    float den = 0.f;
    for (int i = lane; i < deg; i += 32) {
        float a = (i < CAP) ? ch[i]
                            : lrelu(g_asrc2[g_csr_src[beg + i]] + ad);
        float e = expf(a - mx);
        if (i < CAP) ch[i] = e;
        den += e;
    }
#pragma unroll
    for (int o = 16; o > 0; o >>= 1)
        den += __shfl_xor_sync(0xFFFFFFFFu, den, o);
    float rden = 1.f / (den + SM_EPS);
    __syncwarp();

    float acc[4];
#pragma unroll
    for (int j = 0; j < 4; j++) acc[j] = 0.f;
    for (int i = 0; i < deg; i++) {
        int s = g_csr_src[beg + i];
        float w;
        if (i < CAP) w = ch[i] * rden;
        else w = expf(lrelu(g_asrc2[s] + ad) - mx) * rden;
        const float* hr = g_h2 + (size_t)s * C2;
        acc[0] += hr[0 * 32 + lane] * w;
        acc[1] += hr[1 * 32 + lane] * w;
        acc[2] += hr[2 * 32 + lane] * w;
        acc[3] += hr[3 * 32 + lane] * w;
    }
    float* orow = g_out2 + (size_t)n * C2;
#pragma unroll
    for (int j = 0; j < 4; j++) orow[j * 32 + lane] = acc[j];
}

// ---------------- pooling ----------------
__global__ void pool_kernel(const float* __restrict__ bias2,
                            float* __restrict__ out) {
    int i = blockIdx.x * blockDim.x + threadIdx.x;
    if (i >= NN * C2) return;
    int n = i >> 7, c = i & 127;
    float v = fmaxf(g_out2[i] + bias2[c], 0.f);
    atomicAdd(out + g_batch32[n] * C2 + c, v);
}

__global__ void final_kernel(float* __restrict__ out) {
    int i = blockIdx.x * blockDim.x + threadIdx.x;
    if (i < NG * C2) out[i] /= fmaxf((float)g_cnt[i >> 7], 1.f);
}

// ---------------- host launcher ----------------
extern "C" void kernel_launch(void* const* d_in, const int* in_sizes, int n_in,
                              void* d_out, int out_size) {
    // Resolve inputs robustly: unique sizes by value, equal-sized triples in order.
    const void *x = 0, *W1 = 0, *W2 = 0, *ei = 0, *batch = 0;
    const void *t256[3] = {0, 0, 0};  // att_src1, att_dst1, bias1
    const void *t128[3] = {0, 0, 0};  // att_src2, att_dst2, bias2
    int n256 = 0, n128 = 0;
    for (int i = 0; i < n_in; i++) {
        int sz = in_sizes[i];
        if      (sz == NN * CIN)  x = d_in[i];
        else if (sz == CIN * C1)  W1 = d_in[i];
        else if (sz == C1 * C2)   W2 = d_in[i];
        else if (sz == 2 * NE)    ei = d_in[i];
        else if (sz == NN)        batch = d_in[i];
        else if (sz == 256 && n256 < 3) t256[n256++] = d_in[i];
        else if (sz == 128 && n128 < 3) t128[n128++] = d_in[i];
    }
    const float* as1 = (const float*)t256[0];
    const float* ad1 = (const float*)t256[1];
    const float* b1  = (const float*)t256[2];
    const float* as2 = (const float*)t128[0];
    const float* ad2 = (const float*)t128[1];
    const float* b2  = (const float*)t128[2];
    float* out = (float*)d_out;

    probe_kernel<<<1, 32>>>(ei, batch);
    zcnt_kernel<<<1, 128>>>();
    convert_kernel<<<(ET + 255) / 256, 256>>>(ei, batch, out);
    hist_kernel<<<(ET + 255) / 256, 256>>>();
    scan_kernel<<<1, 1024>>>();
    scatter_kernel<<<(ET + 255) / 256, 256>>>();

    // layer 1
    gemm_kernel<1><<<dim3(C1 / 128, (NN + 127) / 128), 256>>>((const float*)x, (const float*)W1, nullptr);
    dots1_kernel<<<NN, 256>>>(as1, ad1);
    agg1_kernel<<<(NN + 7) / 8, 256>>>();

    // layer 2 (relu(out1 + b1) fused into GEMM2 A-load)
    gemm_kernel<2><<<dim3(C2 / 128, (NN + 127) / 128), 256>>>(nullptr, (const float*)W2, b1);
    dots2_kernel<<<NN, 128>>>(as2, ad2);
    agg2_kernel<<<(NN + 7) / 8, 256>>>();

    // mean pool
    pool_kernel<<<(NN * C2 + 255) / 256, 256>>>(b2, out);
    final_kernel<<<(NG * C2 + 255) / 256, 256>>>(out);
}

// round 7
// speedup vs baseline: 1.6161x; 1.0127x over previous
#include <cuda_runtime.h>
#include <math_constants.h>

#define NN 50000
#define NE 800000
#define ET (NE + NN)
#define CIN 256
#define C1 256
#define C2 128
#define NG 100
#define NH 4
#define NEG_SLOPE 0.2f
#define SM_EPS 1e-16f
#define CAP 128   // per-warp alpha cache (avg degree ~17; recompute fallback beyond)

// ---------------- scratch (static device arrays; no allocation) ----------------
__device__ float g_h1[NN * C1];
__device__ float g_out1[NN * C1];
__device__ float g_h2[NN * C2];
__device__ float g_out2[NN * C2];
__device__ float g_asrc1[NN * NH], g_adst1[NN * NH];
__device__ float g_asrc2[NN],      g_adst2[NN];
__device__ int   g_cnt[NG];
__device__ int   g_src[ET], g_dst[ET];
__device__ int   g_batch32[NN];
__device__ int   g_e_is64, g_b_is64;
__device__ int   g_deg[NN];
__device__ int   g_pos[NN];
__device__ int   g_off[NN + 1];
__device__ int   g_csr_src[ET];

// ---------------- probe (dtype sniff) + tiny zeroing ----------------
__global__ void probe_kernel(const void* __restrict__ ei,
                             const void* __restrict__ batch) {
    int t = threadIdx.x;
    for (int i = t; i < NG; i += 32) g_cnt[i] = 0;
    if (t != 0) return;
    const long long* e64 = (const long long*)ei;
    int ok = 1;
    for (int i = 0; i < 256; i++) {
        long long v = e64[i];
        if (v < 0 || v >= NN) { ok = 0; break; }
    }
    g_e_is64 = ok;
    const long long* b64 = (const long long*)batch;
    int okb = 1;
    for (int i = 0; i < 256 && okb; i++) {
        long long v = b64[i];
        if (v < 0 || v >= NG) okb = 0;
    }
    for (int i = NN / 2 - 256; i < NN / 2 && okb; i++) {  // batch sorted: probe tail too
        long long v = b64[i];
        if (v < 0 || v >= NG) okb = 0;
    }
    g_b_is64 = okb;
}

// decode indices, zero per-call scratch, count graph sizes, zero output
__global__ void convert_kernel(const void* __restrict__ ei,
                               const void* __restrict__ batch,
                               float* __restrict__ out) {
    int i = blockIdx.x * blockDim.x + threadIdx.x;
    if (i < ET) {
        int s, d;
        if (i < NE) {
            if (g_e_is64) {
                const long long* p = (const long long*)ei;
                s = (int)p[i]; d = (int)p[NE + i];
            } else {
                const int* p = (const int*)ei;
                s = p[i]; d = p[NE + i];
            }
        } else {
            s = i - NE; d = s;  // appended self-loops
        }
        s = min(max(s, 0), NN - 1);
        d = min(max(d, 0), NN - 1);
        g_src[i] = s; g_dst[i] = d;
    }
    if (i < NN) {
        int b;
        if (g_b_is64) b = (int)((const long long*)batch)[i];
        else          b = ((const int*)batch)[i];
        b = min(max(b, 0), NG - 1);
        g_batch32[i] = b;
        g_deg[i] = 0; g_pos[i] = 0;
        atomicAdd(&g_cnt[b], 1);
    }
    if (i < NG * C2) out[i] = 0.f;
}

// ---------------- CSR build ----------------
__global__ void hist_kernel() {
    int e = blockIdx.x * blockDim.x + threadIdx.x;
    if (e < ET) atomicAdd(&g_deg[g_dst[e]], 1);
}

__global__ void scan_kernel() {
    __shared__ int psum[1024];
    const int CH = (NN + 1023) / 1024;
    int t = threadIdx.x;
    int b = t * CH;
    int sum = 0;
    for (int k = 0; k < CH; k++) {
        int idx = b + k;
        if (idx < NN) sum += g_deg[idx];
    }
    psum[t] = sum;
    __syncthreads();
    for (int off = 1; off < 1024; off <<= 1) {
        int v = (t >= off) ? psum[t - off] : 0;
        __syncthreads();
        psum[t] += v;
        __syncthreads();
    }
    int run = (t > 0) ? psum[t - 1] : 0;
    for (int k = 0; k < CH; k++) {
        int idx = b + k;
        if (idx < NN) { g_off[idx] = run; run += g_deg[idx]; }
    }
    if (t == 1023) g_off[NN] = run;
}

__global__ void scatter_kernel() {
    int e = blockIdx.x * blockDim.x + threadIdx.x;
    if (e >= ET) return;
    int d = g_dst[e];
    int slot = g_off[d] + atomicAdd(&g_pos[d], 1);
    g_csr_src[slot] = g_src[e];
}

// ---------------- SGEMM (double-buffered): C[M,N] = A[M,256] * B[256,N] ----------------
// LAYER==2 fuses A := relu(A + bias) on the fly.
template <int LAYER>
__global__ void __launch_bounds__(256, 2)
gemm_kernel(const float* __restrict__ Ain,
            const float* __restrict__ B,
            const float* __restrict__ bias) {
    constexpr int K = 256;
    constexpr int BK = 16;
    constexpr int NT = K / BK;  // 16 tiles
    constexpr int N = (LAYER == 1) ? C1 : C2;
    constexpr bool FUSE = (LAYER == 2);
    const float* A = (LAYER == 1) ? Ain : g_out1;
    float*       C = (LAYER == 1) ? g_h1 : g_h2;
    const int M = NN;

    __shared__ float As[2][BK][128];  // transposed: As[k][m]
    __shared__ float Bs[2][BK][128];

    int tid = threadIdx.x;
    int m0 = blockIdx.y * 128;
    int n0 = blockIdx.x * 128;
    int ty = tid >> 4, tx = tid & 15;

    // A loader: 128x16 tile, 2 row-halves
    int arow = tid >> 2;            // 0..63
    int acol = (tid & 3) * 4;       // 0,4,8,12
    // B loader: 16x128 tile, 2 row-halves
    int brow = tid >> 5;            // 0..7
    int bcol = (tid & 31) * 4;

    int gr0 = m0 + arow, gr1 = m0 + arow + 64;
    const float* Ar0 = A + (size_t)gr0 * K + acol;
    const float* Ar1 = A + (size_t)gr1 * K + acol;

    float acc[8][8];
#pragma unroll
    for (int i = 0; i < 8; i++)
#pragma unroll
        for (int j = 0; j < 8; j++) acc[i][j] = 0.f;

    float4 sa0, sa1, sb0, sb1;
    auto fetch = [&](int k0) {
        sa0 = make_float4(0.f, 0.f, 0.f, 0.f);
        sa1 = make_float4(0.f, 0.f, 0.f, 0.f);
        if (gr0 < M) sa0 = *(const float4*)(Ar0 + k0);
        if (gr1 < M) sa1 = *(const float4*)(Ar1 + k0);
        if (FUSE) {
            float4 bv = *(const float4*)(bias + k0 + acol);
            sa0.x = fmaxf(sa0.x + bv.x, 0.f); sa0.y = fmaxf(sa0.y + bv.y, 0.f);
            sa0.z = fmaxf(sa0.z + bv.z, 0.f); sa0.w = fmaxf(sa0.w + bv.w, 0.f);
            sa1.x = fmaxf(sa1.x + bv.x, 0.f); sa1.y = fmaxf(sa1.y + bv.y, 0.f);
            sa1.z = fmaxf(sa1.z + bv.z, 0.f); sa1.w = fmaxf(sa1.w + bv.w, 0.f);
        }
        sb0 = *(const float4*)(B + (size_t)(k0 + brow) * N + n0 + bcol);
        sb1 = *(const float4*)(B + (size_t)(k0 + brow + 8) * N + n0 + bcol);
    };
    auto stage = [&](int buf) {
        As[buf][acol + 0][arow] = sa0.x;
        As[buf][acol + 1][arow] = sa0.y;
        As[buf][acol + 2][arow] = sa0.z;
        As[buf][acol + 3][arow] = sa0.w;
        As[buf][acol + 0][arow + 64] = sa1.x;
        As[buf][acol + 1][arow + 64] = sa1.y;
        As[buf][acol + 2][arow + 64] = sa1.z;
        As[buf][acol + 3][arow + 64] = sa1.w;
        *(float4*)&Bs[buf][brow][bcol] = sb0;
        *(float4*)&Bs[buf][brow + 8][bcol] = sb1;
    };

    fetch(0);
    stage(0);
    __syncthreads();

    for (int t = 0; t < NT; t++) {
        int buf = t & 1;
        if (t + 1 < NT) fetch((t + 1) * BK);
#pragma unroll
        for (int k = 0; k < BK; k++) {
            float a[8], b[8];
            *(float4*)(a)     = *(float4*)&As[buf][k][ty * 8];
            *(float4*)(a + 4) = *(float4*)&As[buf][k][ty * 8 + 4];
            *(float4*)(b)     = *(float4*)&Bs[buf][k][tx * 8];
            *(float4*)(b + 4) = *(float4*)&Bs[buf][k][tx * 8 + 4];
#pragma unroll
            for (int i = 0; i < 8; i++)
#pragma unroll
                for (int j = 0; j < 8; j++) acc[i][j] += a[i] * b[j];
        }
        if (t + 1 < NT) {
            stage(buf ^ 1);
            __syncthreads();
        }
    }

#pragma unroll
    for (int i = 0; i < 8; i++) {
        int r = m0 + ty * 8 + i;
        if (r < M) {
            *(float4*)(C + (size_t)r * N + n0 + tx * 8) =
                make_float4(acc[i][0], acc[i][1], acc[i][2], acc[i][3]);
            *(float4*)(C + (size_t)r * N + n0 + tx * 8 + 4) =
                make_float4(acc[i][4], acc[i][5], acc[i][6], acc[i][7]);
        }
    }
}

// ---------------- attention dot products ----------------
__global__ void dots1_kernel(const float* __restrict__ att_src,
                             const float* __restrict__ att_dst) {
    int n = blockIdx.x;
    int c = threadIdx.x;  // 256 threads
    float v = g_h1[n * C1 + c];
    float s = v * att_src[c];
    float d = v * att_dst[c];
#pragma unroll
    for (int o = 16; o > 0; o >>= 1) {
        s += __shfl_xor_sync(0xFFFFFFFFu, s, o);
        d += __shfl_xor_sync(0xFFFFFFFFu, d, o);
    }
    __shared__ float ss[8], sd[8];
    int w = c >> 5;
    if ((c & 31) == 0) { ss[w] = s; sd[w] = d; }
    __syncthreads();
    if (c < NH) {
        g_asrc1[n * NH + c] = ss[2 * c] + ss[2 * c + 1];
        g_adst1[n * NH + c] = sd[2 * c] + sd[2 * c + 1];
    }
}

__global__ void dots2_kernel(const float* __restrict__ att_src,
                             const float* __restrict__ att_dst) {
    int n = blockIdx.x;
    int c = threadIdx.x;  // 128 threads
    float v = g_h2[n * C2 + c];
    float s = v * att_src[c];
    float d = v * att_dst[c];
#pragma unroll
    for (int o = 16; o > 0; o >>= 1) {
        s += __shfl_xor_sync(0xFFFFFFFFu, s, o);
        d += __shfl_xor_sync(0xFFFFFFFFu, d, o);
    }
    __shared__ float ss[4], sd[4];
    if ((c & 31) == 0) { ss[c >> 5] = s; sd[c >> 5] = d; }
    __syncthreads();
    if (c == 0) {
        g_asrc2[n] = ss[0] + ss[1] + ss[2] + ss[3];
        g_adst2[n] = sd[0] + sd[1] + sd[2] + sd[3];
    }
}

// ---------------- fused attention + aggregation (one warp per dst node) ----------------
__device__ __forceinline__ float lrelu(float a) {
    return (a > 0.f) ? a : NEG_SLOPE * a;
}

__global__ void __launch_bounds__(256) agg1_kernel() {
    __shared__ float cache[8][NH * CAP];
    int wid = threadIdx.x >> 5, lane = threadIdx.x & 31;
    int n = blockIdx.x * 8 + wid;
    if (n >= NN) return;
    float* ch = cache[wid];
    int beg = g_off[n], end = g_off[n + 1];
    int deg = end - beg;
    float4 ad = *(const float4*)(g_adst1 + n * 4);

    float mx0 = -CUDART_INF_F, mx1 = -CUDART_INF_F, mx2 = -CUDART_INF_F, mx3 = -CUDART_INF_F;
    for (int i = lane; i < deg; i += 32) {
        int s = g_csr_src[beg + i];
        float4 as = *(const float4*)(g_asrc1 + s * 4);
        float a0 = lrelu(as.x + ad.x), a1 = lrelu(as.y + ad.y);
        float a2 = lrelu(as.z + ad.z), a3 = lrelu(as.w + ad.w);
        if (i < CAP) {
            ch[0 * CAP + i] = a0; ch[1 * CAP + i] = a1;
            ch[2 * CAP + i] = a2; ch[3 * CAP + i] = a3;
        }
        mx0 = fmaxf(mx0, a0); mx1 = fmaxf(mx1, a1);
        mx2 = fmaxf(mx2, a2); mx3 = fmaxf(mx3, a3);
    }
#pragma unroll
    for (int o = 16; o > 0; o >>= 1) {
        mx0 = fmaxf(mx0, __shfl_xor_sync(0xFFFFFFFFu, mx0, o));
        mx1 = fmaxf(mx1, __shfl_xor_sync(0xFFFFFFFFu, mx1, o));
        mx2 = fmaxf(mx2, __shfl_xor_sync(0xFFFFFFFFu, mx2, o));
        mx3 = fmaxf(mx3, __shfl_xor_sync(0xFFFFFFFFu, mx3, o));
    }
    __syncwarp();

    float d0 = 0.f, d1 = 0.f, d2 = 0.f, d3 = 0.f;
    for (int i = lane; i < deg; i += 32) {
        float a0, a1, a2, a3;
        if (i < CAP) {
            a0 = ch[0 * CAP + i]; a1 = ch[1 * CAP + i];
            a2 = ch[2 * CAP + i]; a3 = ch[3 * CAP + i];
        } else {
            int s = g_csr_src[beg + i];
            float4 as = *(const float4*)(g_asrc1 + s * 4);
            a0 = lrelu(as.x + ad.x); a1 = lrelu(as.y + ad.y);
            a2 = lrelu(as.z + ad.z); a3 = lrelu(as.w + ad.w);
        }
        float e0 = expf(a0 - mx0), e1 = expf(a1 - mx1);
        float e2 = expf(a2 - mx2), e3 = expf(a3 - mx3);
        if (i < CAP) {
            ch[0 * CAP + i] = e0; ch[1 * CAP + i] = e1;
            ch[2 * CAP + i] = e2; ch[3 * CAP + i] = e3;
        }
        d0 += e0; d1 += e1; d2 += e2; d3 += e3;
    }
#pragma unroll
    for (int o = 16; o > 0; o >>= 1) {
        d0 += __shfl_xor_sync(0xFFFFFFFFu, d0, o);
        d1 += __shfl_xor_sync(0xFFFFFFFFu, d1, o);
        d2 += __shfl_xor_sync(0xFFFFFFFFu, d2, o);
        d3 += __shfl_xor_sync(0xFFFFFFFFu, d3, o);
    }
    float r0 = 1.f / (d0 + SM_EPS), r1 = 1.f / (d1 + SM_EPS);
    float r2 = 1.f / (d2 + SM_EPS), r3 = 1.f / (d3 + SM_EPS);
    __syncwarp();

    float acc[8];
#pragma unroll
    for (int j = 0; j < 8; j++) acc[j] = 0.f;
    for (int i = 0; i < deg; i++) {
        float w0, w1, w2, w3;
        if (i < CAP) {
            w0 = ch[0 * CAP + i] * r0; w1 = ch[1 * CAP + i] * r1;
            w2 = ch[2 * CAP + i] * r2; w3 = ch[3 * CAP + i] * r3;
        } else {
            int s = g_csr_src[beg + i];
            float4 as = *(const float4*)(g_asrc1 + s * 4);
            w0 = expf(lrelu(as.x + ad.x) - mx0) * r0;
            w1 = expf(lrelu(as.y + ad.y) - mx1) * r1;
            w2 = expf(lrelu(as.z + ad.z) - mx2) * r2;
            w3 = expf(lrelu(as.w + ad.w) - mx3) * r3;
        }
        int s = g_csr_src[beg + i];
        const float* hr = g_h1 + (size_t)s * C1;
        acc[0] += hr[0 * 32 + lane] * w0;
        acc[1] += hr[1 * 32 + lane] * w0;
        acc[2] += hr[2 * 32 + lane] * w1;
        acc[3] += hr[3 * 32 + lane] * w1;
        acc[4] += hr[4 * 32 + lane] * w2;
        acc[5] += hr[5 * 32 + lane] * w2;
        acc[6] += hr[6 * 32 + lane] * w3;
        acc[7] += hr[7 * 32 + lane] * w3;
    }
    float* orow = g_out1 + (size_t)n * C1;
#pragma unroll
    for (int j = 0; j < 8; j++) orow[j * 32 + lane] = acc[j];
}

__global__ void __launch_bounds__(256) agg2_kernel() {
    __shared__ float cache[8][CAP];
    int wid = threadIdx.x >> 5, lane = threadIdx.x & 31;
    int n = blockIdx.x * 8 + wid;
    if (n >= NN) return;
    float* ch = cache[wid];
    int beg = g_off[n], end = g_off[n + 1];
    int deg = end - beg;
    float ad = g_adst2[n];

    float mx = -CUDART_INF_F;
    for (int i = lane; i < deg; i += 32) {
        float a = lrelu(g_asrc2[g_csr_src[beg + i]] + ad);
        if (i < CAP) ch[i] = a;
        mx = fmaxf(mx, a);
    }
#pragma unroll
    for (int o = 16; o > 0; o >>= 1)
        mx = fmaxf(mx, __shfl_xor_sync(0xFFFFFFFFu, mx, o));
    __syncwarp();

    float den = 0.f;
    for (int i = lane; i < deg; i += 32) {
        float a = (i < CAP) ? ch[i]
                            : lrelu(g_asrc2[g_csr_src[beg + i]] + ad);
        float e = expf(a - mx);
        if (i < CAP) ch[i] = e;
        den += e;
    }
#pragma unroll
    for (int o = 16; o > 0; o >>= 1)
        den += __shfl_xor_sync(0xFFFFFFFFu, den, o);
    float rden = 1.f / (den + SM_EPS);
    __syncwarp();

    float acc[4];
#pragma unroll
    for (int j = 0; j < 4; j++) acc[j] = 0.f;
    for (int i = 0; i < deg; i++) {
        int s = g_csr_src[beg + i];
        float w;
        if (i < CAP) w = ch[i] * rden;
        else w = expf(lrelu(g_asrc2[s] + ad) - mx) * rden;
        const float* hr = g_h2 + (size_t)s * C2;
        acc[0] += hr[0 * 32 + lane] * w;
        acc[1] += hr[1 * 32 + lane] * w;
        acc[2] += hr[2 * 32 + lane] * w;
        acc[3] += hr[3 * 32 + lane] * w;
    }
    float* orow = g_out2 + (size_t)n * C2;
#pragma unroll
    for (int j = 0; j < 4; j++) orow[j * 32 + lane] = acc[j];
}

// ---------------- pooling (batch is sorted: register-accumulate, flush on change) ----
__global__ void pool_kernel(const float* __restrict__ bias2,
                            float* __restrict__ out) {
    int c = threadIdx.x;            // 128 channels
    int n0 = blockIdx.x * 128;
    int nend = min(n0 + 128, NN);
    float bval = bias2[c];
    float acc = 0.f;
    int cur = g_batch32[n0];
    for (int n = n0; n < nend; n++) {
        int b = g_batch32[n];
        if (b != cur) {
            atomicAdd(out + cur * C2 + c, acc);
            acc = 0.f; cur = b;
        }
        acc += fmaxf(g_out2[(size_t)n * C2 + c] + bval, 0.f);
    }
    atomicAdd(out + cur * C2 + c, acc);
}

__global__ void final_kernel(float* __restrict__ out) {
    int i = blockIdx.x * blockDim.x + threadIdx.x;
    if (i < NG * C2) out[i] /= fmaxf((float)g_cnt[i >> 7], 1.f);
}

// ---------------- host launcher ----------------
extern "C" void kernel_launch(void* const* d_in, const int* in_sizes, int n_in,
                              void* d_out, int out_size) {
    const void *x = 0, *W1 = 0, *W2 = 0, *ei = 0, *batch = 0;
    const void *t256[3] = {0, 0, 0};
    const void *t128[3] = {0, 0, 0};
    int n256 = 0, n128 = 0;
    for (int i = 0; i < n_in; i++) {
        int sz = in_sizes[i];
        if      (sz == NN * CIN)  x = d_in[i];
        else if (sz == CIN * C1)  W1 = d_in[i];
        else if (sz == C1 * C2)   W2 = d_in[i];
        else if (sz == 2 * NE)    ei = d_in[i];
        else if (sz == NN)        batch = d_in[i];
        else if (sz == 256 && n256 < 3) t256[n256++] = d_in[i];
        else if (sz == 128 && n128 < 3) t128[n128++] = d_in[i];
    }
    const float* as1 = (const float*)t256[0];
    const float* ad1 = (const float*)t256[1];
    const float* b1  = (const float*)t256[2];
    const float* as2 = (const float*)t128[0];
    const float* ad2 = (const float*)t128[1];
    const float* b2  = (const float*)t128[2];
    float* out = (float*)d_out;

    // launches 1-5 (setup) so that launch 6 = gemm1 lands under ncu -s 5 -c 1
    probe_kernel<<<1, 32>>>(ei, batch);
    convert_kernel<<<(ET + 255) / 256, 256>>>(ei, batch, out);
    hist_kernel<<<(ET + 255) / 256, 256>>>();
    scan_kernel<<<1, 1024>>>();
    scatter_kernel<<<(ET + 255) / 256, 256>>>();

    // layer 1
    gemm_kernel<1><<<dim3(C1 / 128, (NN + 127) / 128), 256>>>((const float*)x, (const float*)W1, nullptr);
    dots1_kernel<<<NN, 256>>>(as1, ad1);
    agg1_kernel<<<(NN + 7) / 8, 256>>>();

    // layer 2 (relu(out1 + b1) fused into GEMM2 A-load)
    gemm_kernel<2><<<dim3(C2 / 128, (NN + 127) / 128), 256>>>(nullptr, (const float*)W2, b1);
    dots2_kernel<<<NN, 128>>>(as2, ad2);
    agg2_kernel<<<(NN + 7) / 8, 256>>>();

    // mean pool
    pool_kernel<<<(NN + 127) / 128, 128>>>(b2, out);
    final_kernel<<<(NG * C2 + 255) / 256, 256>>>(out);
}

// round 8
// speedup vs baseline: 1.8773x; 1.1616x over previous
#include <cuda_runtime.h>
#include <math_constants.h>

#define NN 50000
#define NE 800000
#define ET (NE + NN)
#define CIN 256
#define C1 256
#define C2 128
#define NG 100
#define NH 4
#define NEG_SLOPE 0.2f
#define SM_EPS 1e-16f
#define CAP 128    // per-warp alpha cache (avg degree ~17; recompute fallback beyond)
#define SBLK 49    // scan blocks: 49 * 1024 >= NN

// ---------------- scratch (static device arrays; no allocation) ----------------
__device__ float g_h1[NN * C1];
__device__ float g_out1[NN * C1];
__device__ float g_h2[NN * C2];
__device__ float g_out2[NN * C2];
__device__ float g_asrc1[NN * NH], g_adst1[NN * NH];
__device__ float g_asrc2[NN],      g_adst2[NN];
__device__ int   g_cnt[NG];
__device__ int   g_batch32[NN];
__device__ int   g_e_is64, g_b_is64;
__device__ int   g_deg[NN];
__device__ int   g_pos[NN];
__device__ int   g_off[NN + 1];
__device__ int   g_srcd[ET], g_dstd[ET];   // decoded endpoints
__device__ int   g_csr_src[ET];
__device__ int   g_bsum[SBLK], g_bsumx[SBLK];

// ---------------- zero scratch counters ----------------
__global__ void zdeg_kernel() {
    int i = blockIdx.x * blockDim.x + threadIdx.x;
    if (i < NN) { g_deg[i] = 0; g_pos[i] = 0; }
    if (i < NG) g_cnt[i] = 0;
}

// ---------------- parallel dtype probe ----------------
// Edge values are random in [0,NN): int32 data viewed as int64 packs two
// values -> >= 2^32 -> detected. Batch is SORTED: also probe the tail
// window [NN/2-256, NN/2) where int32 data packs values ~99 -> >= 2^32.
__global__ void probe_kernel(const void* __restrict__ ei,
                             const void* __restrict__ batch) {
    __shared__ int eok, bok;
    int t = threadIdx.x;  // 256 threads
    if (t == 0) { eok = 1; bok = 1; }
    __syncthreads();
    const long long* e64 = (const long long*)ei;
    long long v = e64[t];
    if (v < 0 || v >= NN) eok = 0;           // benign race: all write 0
    const long long* b64 = (const long long*)batch;
    long long u = b64[t];
    if (u < 0 || u >= NG) bok = 0;
    long long w = b64[NN / 2 - 256 + t];
    if (w < 0 || w >= NG) bok = 0;
    __syncthreads();
    if (t == 0) { g_e_is64 = eok; g_b_is64 = bok; }
}

// decode indices, build degree histogram, decode batch, zero output
__global__ void convert_kernel(const void* __restrict__ ei,
                               const void* __restrict__ batch,
                               float* __restrict__ out) {
    int i = blockIdx.x * blockDim.x + threadIdx.x;
    if (i < ET) {
        int s, d;
        if (i < NE) {
            if (g_e_is64) {
                const long long* p = (const long long*)ei;
                s = (int)p[i]; d = (int)p[NE + i];
            } else {
                const int* p = (const int*)ei;
                s = p[i]; d = p[NE + i];
            }
        } else {
            s = i - NE; d = s;  // appended self-loops
        }
        s = min(max(s, 0), NN - 1);
        d = min(max(d, 0), NN - 1);
        g_srcd[i] = s; g_dstd[i] = d;
        atomicAdd(&g_deg[d], 1);
    }
    if (i < NN) {
        int b;
        if (g_b_is64) b = (int)((const long long*)batch)[i];
        else          b = ((const int*)batch)[i];
        b = min(max(b, 0), NG - 1);
        g_batch32[i] = b;
        atomicAdd(&g_cnt[b], 1);
    }
    if (i < NG * C2) out[i] = 0.f;
}

// ---------------- two-level exclusive scan of g_deg -> g_off ----------------
__global__ void scanA_kernel() {  // grid SBLK, block 256; 1024 elems/block
    __shared__ int tsum[256];
    int b = blockIdx.x, t = threadIdx.x;
    int base = b * 1024 + t * 4;
    int v0 = 0, v1 = 0, v2 = 0, v3 = 0;
    if (base + 0 < NN) v0 = g_deg[base + 0];
    if (base + 1 < NN) v1 = g_deg[base + 1];
    if (base + 2 < NN) v2 = g_deg[base + 2];
    if (base + 3 < NN) v3 = g_deg[base + 3];
    tsum[t] = v0 + v1 + v2 + v3;
    __syncthreads();
#pragma unroll
    for (int off = 1; off < 256; off <<= 1) {
        int x = (t >= off) ? tsum[t - off] : 0;
        __syncthreads();
        tsum[t] += x;
        __syncthreads();
    }
    int run = (t > 0) ? tsum[t - 1] : 0;
    if (base + 0 < NN) { g_off[base + 0] = run; run += v0; }
    if (base + 1 < NN) { g_off[base + 1] = run; run += v1; }
    if (base + 2 < NN) { g_off[base + 2] = run; run += v2; }
    if (base + 3 < NN) { g_off[base + 3] = run; run += v3; }
    if (t == 255) g_bsum[b] = tsum[255];
}

__global__ void scanB_kernel() {  // 1 block, 64 threads: scan SBLK sums
    __shared__ int sh[64];
    int t = threadIdx.x;
    sh[t] = (t < SBLK) ? g_bsum[t] : 0;
    __syncthreads();
#pragma unroll
    for (int off = 1; off < 64; off <<= 1) {
        int x = (t >= off) ? sh[t - off] : 0;
        __syncthreads();
        sh[t] += x;
        __syncthreads();
    }
    if (t < SBLK) g_bsumx[t] = (t > 0) ? sh[t - 1] : 0;
}

__global__ void scanC_kernel() {  // add block offsets
    int i = blockIdx.x * blockDim.x + threadIdx.x;
    if (i < NN) g_off[i] += g_bsumx[i >> 10];
    if (i == 0) g_off[NN] = ET;   // degrees always sum to ET
}

__global__ void scatter_kernel() {
    int e = blockIdx.x * blockDim.x + threadIdx.x;
    if (e >= ET) return;
    int d = g_dstd[e];
    int slot = g_off[d] + atomicAdd(&g_pos[d], 1);
    g_csr_src[slot] = g_srcd[e];
}

// ---------------- SGEMM (double-buffered): C[M,N] = A[M,256] * B[256,N] ----------------
template <int LAYER>
__global__ void __launch_bounds__(256, 2)
gemm_kernel(const float* __restrict__ Ain,
            const float* __restrict__ B,
            const float* __restrict__ bias) {
    constexpr int K = 256;
    constexpr int BK = 16;
    constexpr int NT = K / BK;
    constexpr int N = (LAYER == 1) ? C1 : C2;
    constexpr bool FUSE = (LAYER == 2);
    const float* A = (LAYER == 1) ? Ain : g_out1;
    float*       C = (LAYER == 1) ? g_h1 : g_h2;
    const int M = NN;

    __shared__ float As[2][BK][128];
    __shared__ float Bs[2][BK][128];

    int tid = threadIdx.x;
    int m0 = blockIdx.y * 128;
    int n0 = blockIdx.x * 128;
    int ty = tid >> 4, tx = tid & 15;

    int arow = tid >> 2;
    int acol = (tid & 3) * 4;
    int brow = tid >> 5;
    int bcol = (tid & 31) * 4;

    int gr0 = m0 + arow, gr1 = m0 + arow + 64;
    const float* Ar0 = A + (size_t)gr0 * K + acol;
    const float* Ar1 = A + (size_t)gr1 * K + acol;

    float acc[8][8];
#pragma unroll
    for (int i = 0; i < 8; i++)
#pragma unroll
        for (int j = 0; j < 8; j++) acc[i][j] = 0.f;

    float4 sa0, sa1, sb0, sb1;
    auto fetch = [&](int k0) {
        sa0 = make_float4(0.f, 0.f, 0.f, 0.f);
        sa1 = make_float4(0.f, 0.f, 0.f, 0.f);
        if (gr0 < M) sa0 = *(const float4*)(Ar0 + k0);
        if (gr1 < M) sa1 = *(const float4*)(Ar1 + k0);
        if (FUSE) {
            float4 bv = *(const float4*)(bias + k0 + acol);
            sa0.x = fmaxf(sa0.x + bv.x, 0.f); sa0.y = fmaxf(sa0.y + bv.y, 0.f);
            sa0.z = fmaxf(sa0.z + bv.z, 0.f); sa0.w = fmaxf(sa0.w + bv.w, 0.f);
            sa1.x = fmaxf(sa1.x + bv.x, 0.f); sa1.y = fmaxf(sa1.y + bv.y, 0.f);
            sa1.z = fmaxf(sa1.z + bv.z, 0.f); sa1.w = fmaxf(sa1.w + bv.w, 0.f);
        }
        sb0 = *(const float4*)(B + (size_t)(k0 + brow) * N + n0 + bcol);
        sb1 = *(const float4*)(B + (size_t)(k0 + brow + 8) * N + n0 + bcol);
    };
    auto stage = [&](int buf) {
        As[buf][acol + 0][arow] = sa0.x;
        As[buf][acol + 1][arow] = sa0.y;
        As[buf][acol + 2][arow] = sa0.z;
        As[buf][acol + 3][arow] = sa0.w;
        As[buf][acol + 0][arow + 64] = sa1.x;
        As[buf][acol + 1][arow + 64] = sa1.y;
        As[buf][acol + 2][arow + 64] = sa1.z;
        As[buf][acol + 3][arow + 64] = sa1.w;
        *(float4*)&Bs[buf][brow][bcol] = sb0;
        *(float4*)&Bs[buf][brow + 8][bcol] = sb1;
    };

    fetch(0);
    stage(0);
    __syncthreads();

    for (int t = 0; t < NT; t++) {
        int buf = t & 1;
        if (t + 1 < NT) fetch((t + 1) * BK);
#pragma unroll
        for (int k = 0; k < BK; k++) {
            float a[8], b[8];
            *(float4*)(a)     = *(float4*)&As[buf][k][ty * 8];
            *(float4*)(a + 4) = *(float4*)&As[buf][k][ty * 8 + 4];
            *(float4*)(b)     = *(float4*)&Bs[buf][k][tx * 8];
            *(float4*)(b + 4) = *(float4*)&Bs[buf][k][tx * 8 + 4];
#pragma unroll
            for (int i = 0; i < 8; i++)
#pragma unroll
                for (int j = 0; j < 8; j++) acc[i][j] += a[i] * b[j];
        }
        if (t + 1 < NT) {
            stage(buf ^ 1);
            __syncthreads();
        }
    }

#pragma unroll
    for (int i = 0; i < 8; i++) {
        int r = m0 + ty * 8 + i;
        if (r < M) {
            *(float4*)(C + (size_t)r * N + n0 + tx * 8) =
                make_float4(acc[i][0], acc[i][1], acc[i][2], acc[i][3]);
            *(float4*)(C + (size_t)r * N + n0 + tx * 8 + 4) =
                make_float4(acc[i][4], acc[i][5], acc[i][6], acc[i][7]);
        }
    }
}

// ---------------- attention dot products ----------------
__global__ void dots1_kernel(const float* __restrict__ att_src,
                             const float* __restrict__ att_dst) {
    int n = blockIdx.x;
    int c = threadIdx.x;  // 256 threads
    float v = g_h1[n * C1 + c];
    float s = v * att_src[c];
    float d = v * att_dst[c];
#pragma unroll
    for (int o = 16; o > 0; o >>= 1) {
        s += __shfl_xor_sync(0xFFFFFFFFu, s, o);
        d += __shfl_xor_sync(0xFFFFFFFFu, d, o);
    }
    __shared__ float ss[8], sd[8];
    int w = c >> 5;
    if ((c & 31) == 0) { ss[w] = s; sd[w] = d; }
    __syncthreads();
    if (c < NH) {
        g_asrc1[n * NH + c] = ss[2 * c] + ss[2 * c + 1];
        g_adst1[n * NH + c] = sd[2 * c] + sd[2 * c + 1];
    }
}

__global__ void dots2_kernel(const float* __restrict__ att_src,
                             const float* __restrict__ att_dst) {
    int n = blockIdx.x;
    int c = threadIdx.x;  // 128 threads
    float v = g_h2[n * C2 + c];
    float s = v * att_src[c];
    float d = v * att_dst[c];
#pragma unroll
    for (int o = 16; o > 0; o >>= 1) {
        s += __shfl_xor_sync(0xFFFFFFFFu, s, o);
        d += __shfl_xor_sync(0xFFFFFFFFu, d, o);
    }
    __shared__ float ss[4], sd[4];
    if ((c & 31) == 0) { ss[c >> 5] = s; sd[c >> 5] = d; }
    __syncthreads();
    if (c == 0) {
        g_asrc2[n] = ss[0] + ss[1] + ss[2] + ss[3];
        g_adst2[n] = sd[0] + sd[1] + sd[2] + sd[3];
    }
}

// ---------------- fused attention + aggregation (one warp per dst node) ----------------
__device__ __forceinline__ float lrelu(float a) {
    return (a > 0.f) ? a : NEG_SLOPE * a;
}

__global__ void __launch_bounds__(256) agg1_kernel() {
    __shared__ float cache[8][NH * CAP];
    int wid = threadIdx.x >> 5, lane = threadIdx.x & 31;
    int n = blockIdx.x * 8 + wid;
    if (n >= NN) return;
    float* ch = cache[wid];
    int beg = g_off[n], end = g_off[n + 1];
    int deg = end - beg;
    float4 ad = *(const float4*)(g_adst1 + n * 4);

    float mx0 = -CUDART_INF_F, mx1 = -CUDART_INF_F, mx2 = -CUDART_INF_F, mx3 = -CUDART_INF_F;
    for (int i = lane; i < deg; i += 32) {
        int s = g_csr_src[beg + i];
        float4 as = *(const float4*)(g_asrc1 + s * 4);
        float a0 = lrelu(as.x + ad.x), a1 = lrelu(as.y + ad.y);
        float a2 = lrelu(as.z + ad.z), a3 = lrelu(as.w + ad.w);
        if (i < CAP) {
            ch[0 * CAP + i] = a0; ch[1 * CAP + i] = a1;
            ch[2 * CAP + i] = a2; ch[3 * CAP + i] = a3;
        }
        mx0 = fmaxf(mx0, a0); mx1 = fmaxf(mx1, a1);
        mx2 = fmaxf(mx2, a2); mx3 = fmaxf(mx3, a3);
    }
#pragma unroll
    for (int o = 16; o > 0; o >>= 1) {
        mx0 = fmaxf(mx0, __shfl_xor_sync(0xFFFFFFFFu, mx0, o));
        mx1 = fmaxf(mx1, __shfl_xor_sync(0xFFFFFFFFu, mx1, o));
        mx2 = fmaxf(mx2, __shfl_xor_sync(0xFFFFFFFFu, mx2, o));
        mx3 = fmaxf(mx3, __shfl_xor_sync(0xFFFFFFFFu, mx3, o));
    }
    __syncwarp();

    float d0 = 0.f, d1 = 0.f, d2 = 0.f, d3 = 0.f;
    for (int i = lane; i < deg; i += 32) {
        float a0, a1, a2, a3;
        if (i < CAP) {
            a0 = ch[0 * CAP + i]; a1 = ch[1 * CAP + i];
            a2 = ch[2 * CAP + i]; a3 = ch[3 * CAP + i];
        } else {
            int s = g_csr_src[beg + i];
            float4 as = *(const float4*)(g_asrc1 + s * 4);
            a0 = lrelu(as.x + ad.x); a1 = lrelu(as.y + ad.y);
            a2 = lrelu(as.z + ad.z); a3 = lrelu(as.w + ad.w);
        }
        float e0 = expf(a0 - mx0), e1 = expf(a1 - mx1);
        float e2 = expf(a2 - mx2), e3 = expf(a3 - mx3);
        if (i < CAP) {
            ch[0 * CAP + i] = e0; ch[1 * CAP + i] = e1;
            ch[2 * CAP + i] = e2; ch[3 * CAP + i] = e3;
        }
        d0 += e0; d1 += e1; d2 += e2; d3 += e3;
    }
#pragma unroll
    for (int o = 16; o > 0; o >>= 1) {
        d0 += __shfl_xor_sync(0xFFFFFFFFu, d0, o);
        d1 += __shfl_xor_sync(0xFFFFFFFFu, d1, o);
        d2 += __shfl_xor_sync(0xFFFFFFFFu, d2, o);
        d3 += __shfl_xor_sync(0xFFFFFFFFu, d3, o);
    }
    float r0 = 1.f / (d0 + SM_EPS), r1 = 1.f / (d1 + SM_EPS);
    float r2 = 1.f / (d2 + SM_EPS), r3 = 1.f / (d3 + SM_EPS);
    __syncwarp();

    float acc[8];
#pragma unroll
    for (int j = 0; j < 8; j++) acc[j] = 0.f;
    for (int i = 0; i < deg; i++) {
        float w0, w1, w2, w3;
        if (i < CAP) {
            w0 = ch[0 * CAP + i] * r0; w1 = ch[1 * CAP + i] * r1;
            w2 = ch[2 * CAP + i] * r2; w3 = ch[3 * CAP + i] * r3;
        } else {
            int s = g_csr_src[beg + i];
            float4 as = *(const float4*)(g_asrc1 + s * 4);
            w0 = expf(lrelu(as.x + ad.x) - mx0) * r0;
            w1 = expf(lrelu(as.y + ad.y) - mx1) * r1;
            w2 = expf(lrelu(as.z + ad.z) - mx2) * r2;
            w3 = expf(lrelu(as.w + ad.w) - mx3) * r3;
        }
        int s = g_csr_src[beg + i];
        const float* hr = g_h1 + (size_t)s * C1;
        acc[0] += hr[0 * 32 + lane] * w0;
        acc[1] += hr[1 * 32 + lane] * w0;
        acc[2] += hr[2 * 32 + lane] * w1;
        acc[3] += hr[3 * 32 + lane] * w1;
        acc[4] += hr[4 * 32 + lane] * w2;
        acc[5] += hr[5 * 32 + lane] * w2;
        acc[6] += hr[6 * 32 + lane] * w3;
        acc[7] += hr[7 * 32 + lane] * w3;
    }
    float* orow = g_out1 + (size_t)n * C1;
#pragma unroll
    for (int j = 0; j < 8; j++) orow[j * 32 + lane] = acc[j];
}

__global__ void __launch_bounds__(256) agg2_kernel() {
    __shared__ float cache[8][CAP];
    int wid = threadIdx.x >> 5, lane = threadIdx.x & 31;
    int n = blockIdx.x * 8 + wid;
    if (n >= NN) return;
    float* ch = cache[wid];
    int beg = g_off[n], end = g_off[n + 1];
    int deg = end - beg;
    float ad = g_adst2[n];

    float mx = -CUDART_INF_F;
    for (int i = lane; i < deg; i += 32) {
        float a = lrelu(g_asrc2[g_csr_src[beg + i]] + ad);
        if (i < CAP) ch[i] = a;
        mx = fmaxf(mx, a);
    }
#pragma unroll
    for (int o = 16; o > 0; o >>= 1)
        mx = fmaxf(mx, __shfl_xor_sync(0xFFFFFFFFu, mx, o));
    __syncwarp();

    float den = 0.f;
    for (int i = lane; i < deg; i += 32) {
        float a = (i < CAP) ? ch[i]
                            : lrelu(g_asrc2[g_csr_src[beg + i]] + ad);
        float e = expf(a - mx);
        if (i < CAP) ch[i] = e;
        den += e;
    }
#pragma unroll
    for (int o = 16; o > 0; o >>= 1)
        den += __shfl_xor_sync(0xFFFFFFFFu, den, o);
    float rden = 1.f / (den + SM_EPS);
    __syncwarp();

    float acc[4];
#pragma unroll
    for (int j = 0; j < 4; j++) acc[j] = 0.f;
    for (int i = 0; i < deg; i++) {
        int s = g_csr_src[beg + i];
        float w;
        if (i < CAP) w = ch[i] * rden;
        else w = expf(lrelu(g_asrc2[s] + ad) - mx) * rden;
        const float* hr = g_h2 + (size_t)s * C2;
        acc[0] += hr[0 * 32 + lane] * w;
        acc[1] += hr[1 * 32 + lane] * w;
        acc[2] += hr[2 * 32 + lane] * w;
        acc[3] += hr[3 * 32 + lane] * w;
    }
    float* orow = g_out2 + (size_t)n * C2;
#pragma unroll
    for (int j = 0; j < 4; j++) orow[j * 32 + lane] = acc[j];
}

// ---------------- pooling (batch sorted: register-accumulate, flush on change) ----
__global__ void pool_kernel(const float* __restrict__ bias2,
                            float* __restrict__ out) {
    int c = threadIdx.x;            // 128 channels
    int n0 = blockIdx.x * 128;
    int nend = min(n0 + 128, NN);
    float bval = bias2[c];
    float acc = 0.f;
    int cur = g_batch32[n0];
    for (int n = n0; n < nend; n++) {
        int b = g_batch32[n];
        if (b != cur) {
            atomicAdd(out + cur * C2 + c, acc);
            acc = 0.f; cur = b;
        }
        acc += fmaxf(g_out2[(size_t)n * C2 + c] + bval, 0.f);
    }
    atomicAdd(out + cur * C2 + c, acc);
}

__global__ void final_kernel(float* __restrict__ out) {
    int i = blockIdx.x * blockDim.x + threadIdx.x;
    if (i < NG * C2) out[i] /= fmaxf((float)g_cnt[i >> 7], 1.f);
}

// ---------------- host launcher ----------------
extern "C" void kernel_launch(void* const* d_in, const int* in_sizes, int n_in,
                              void* d_out, int out_size) {
    const void *x = 0, *W1 = 0, *W2 = 0, *ei = 0, *batch = 0;
    const void *t256[3] = {0, 0, 0};
    const void *t128[3] = {0, 0, 0};
    int n256 = 0, n128 = 0;
    for (int i = 0; i < n_in; i++) {
        int sz = in_sizes[i];
        if      (sz == NN * CIN)  x = d_in[i];
        else if (sz == CIN * C1)  W1 = d_in[i];
        else if (sz == C1 * C2)   W2 = d_in[i];
        else if (sz == 2 * NE)    ei = d_in[i];
        else if (sz == NN)        batch = d_in[i];
        else if (sz == 256 && n256 < 3) t256[n256++] = d_in[i];
        else if (sz == 128 && n128 < 3) t128[n128++] = d_in[i];
    }
    const float* as1 = (const float*)t256[0];
    const float* ad1 = (const float*)t256[1];
    const float* b1  = (const float*)t256[2];
    const float* as2 = (const float*)t128[0];
    const float* ad2 = (const float*)t128[1];
    const float* b2  = (const float*)t128[2];
    float* out = (float*)d_out;

    // setup: zero, probe, decode+hist, scan, scatter
    zdeg_kernel<<<(NN + 255) / 256, 256>>>();
    probe_kernel<<<1, 256>>>(ei, batch);
    convert_kernel<<<(ET + 255) / 256, 256>>>(ei, batch, out);
    scanA_kernel<<<SBLK, 256>>>();
    scanB_kernel<<<1, 64>>>();
    scanC_kernel<<<(NN + 255) / 256, 256>>>();
    scatter_kernel<<<(ET + 255) / 256, 256>>>();

    // layer 1
    gemm_kernel<1><<<dim3(C1 / 128, (NN + 127) / 128), 256>>>((const float*)x, (const float*)W1, nullptr);
    dots1_kernel<<<NN, 256>>>(as1, ad1);
    agg1_kernel<<<(NN + 7) / 8, 256>>>();

    // layer 2 (relu(out1 + b1) fused into GEMM2 A-load)
    gemm_kernel<2><<<dim3(C2 / 128, (NN + 127) / 128), 256>>>(nullptr, (const float*)W2, b1);
    dots2_kernel<<<NN, 128>>>(as2, ad2);
    agg2_kernel<<<(NN + 7) / 8, 256>>>();

    // mean pool
    pool_kernel<<<(NN + 127) / 128, 128>>>(b2, out);
    final_kernel<<<(NG * C2 + 255) / 256, 256>>>(out);
}

// round 9
// speedup vs baseline: 2.7359x; 1.4574x over previous
#include <cuda_runtime.h>
#include <math_constants.h>

#define NN 50000
#define NE 800000
#define ET (NE + NN)
#define CIN 256
#define C1 256
#define C2 128
#define NG 100
#define NH 4
#define NEG_SLOPE 0.2f
#define SM_EPS 1e-16f
#define CAP 128    // per-warp alpha cache (avg degree ~17; recompute fallback beyond)
#define SBLK 49    // scan blocks: 49 * 1024 >= NN

// ---------------- scratch (static device arrays; no allocation) ----------------
__device__ float g_h1[NN * C1];
__device__ float g_out1[NN * C1];
__device__ float g_h2[NN * C2];
__device__ float g_out2[NN * C2];
__device__ float g_asrc1[NN * NH], g_adst1[NN * NH];
__device__ float g_asrc2[NN],      g_adst2[NN];
__device__ int   g_cnt[NG];
__device__ int   g_batch32[NN];
__device__ int   g_e_is64, g_b_is64;
__device__ int   g_deg[NN];
__device__ int   g_pos[NN];
__device__ int   g_off[NN + 1];
__device__ int   g_srcd[ET], g_dstd[ET];
__device__ int   g_csr_src[ET];
__device__ int   g_bsum[SBLK], g_bsumx[SBLK];

// ---------------- zero scratch counters ----------------
__global__ void zdeg_kernel() {
    int i = blockIdx.x * blockDim.x + threadIdx.x;
    if (i < NN) { g_deg[i] = 0; g_pos[i] = 0; }
    if (i < NG) g_cnt[i] = 0;
}

// ---------------- parallel dtype probe ----------------
__global__ void probe_kernel(const void* __restrict__ ei,
                             const void* __restrict__ batch) {
    __shared__ int eok, bok;
    int t = threadIdx.x;  // 256 threads
    if (t == 0) { eok = 1; bok = 1; }
    __syncthreads();
    const long long* e64 = (const long long*)ei;
    long long v = e64[t];
    if (v < 0 || v >= NN) eok = 0;
    const long long* b64 = (const long long*)batch;
    long long u = b64[t];
    if (u < 0 || u >= NG) bok = 0;
    long long w = b64[NN / 2 - 256 + t];  // batch sorted: probe tail window too
    if (w < 0 || w >= NG) bok = 0;
    __syncthreads();
    if (t == 0) { g_e_is64 = eok; g_b_is64 = bok; }
}

// decode indices, build degree histogram, decode batch, zero output
__global__ void convert_kernel(const void* __restrict__ ei,
                               const void* __restrict__ batch,
                               float* __restrict__ out) {
    int i = blockIdx.x * blockDim.x + threadIdx.x;
    if (i < ET) {
        int s, d;
        if (i < NE) {
            if (g_e_is64) {
                const long long* p = (const long long*)ei;
                s = (int)p[i]; d = (int)p[NE + i];
            } else {
                const int* p = (const int*)ei;
                s = p[i]; d = p[NE + i];
            }
        } else {
            s = i - NE; d = s;
        }
        s = min(max(s, 0), NN - 1);
        d = min(max(d, 0), NN - 1);
        g_srcd[i] = s; g_dstd[i] = d;
        atomicAdd(&g_deg[d], 1);
    }
    if (i < NN) {
        int b;
        if (g_b_is64) b = (int)((const long long*)batch)[i];
        else          b = ((const int*)batch)[i];
        b = min(max(b, 0), NG - 1);
        g_batch32[i] = b;
        atomicAdd(&g_cnt[b], 1);
    }
    if (i < NG * C2) out[i] = 0.f;
}

// ---------------- two-level exclusive scan of g_deg -> g_off ----------------
__global__ void scanA_kernel() {
    __shared__ int tsum[256];
    int b = blockIdx.x, t = threadIdx.x;
    int base = b * 1024 + t * 4;
    int v0 = 0, v1 = 0, v2 = 0, v3 = 0;
    if (base + 0 < NN) v0 = g_deg[base + 0];
    if (base + 1 < NN) v1 = g_deg[base + 1];
    if (base + 2 < NN) v2 = g_deg[base + 2];
    if (base + 3 < NN) v3 = g_deg[base + 3];
    tsum[t] = v0 + v1 + v2 + v3;
    __syncthreads();
#pragma unroll
    for (int off = 1; off < 256; off <<= 1) {
        int x = (t >= off) ? tsum[t - off] : 0;
        __syncthreads();
        tsum[t] += x;
        __syncthreads();
    }
    int run = (t > 0) ? tsum[t - 1] : 0;
    if (base + 0 < NN) { g_off[base + 0] = run; run += v0; }
    if (base + 1 < NN) { g_off[base + 1] = run; run += v1; }
    if (base + 2 < NN) { g_off[base + 2] = run; run += v2; }
    if (base + 3 < NN) { g_off[base + 3] = run; run += v3; }
    if (t == 255) g_bsum[b] = tsum[255];
}

__global__ void scanB_kernel() {
    __shared__ int sh[64];
    int t = threadIdx.x;
    sh[t] = (t < SBLK) ? g_bsum[t] : 0;
    __syncthreads();
#pragma unroll
    for (int off = 1; off < 64; off <<= 1) {
        int x = (t >= off) ? sh[t - off] : 0;
        __syncthreads();
        sh[t] += x;
        __syncthreads();
    }
    if (t < SBLK) g_bsumx[t] = (t > 0) ? sh[t - 1] : 0;
}

__global__ void scanC_kernel() {
    int i = blockIdx.x * blockDim.x + threadIdx.x;
    if (i < NN) g_off[i] += g_bsumx[i >> 10];
    if (i == 0) g_off[NN] = ET;
}

__global__ void scatter_kernel() {
    int e = blockIdx.x * blockDim.x + threadIdx.x;
    if (e >= ET) return;
    int d = g_dstd[e];
    int slot = g_off[d] + atomicAdd(&g_pos[d], 1);
    g_csr_src[slot] = g_srcd[e];
}

// ---------------- TF32 tensor-core GEMM: C[M,N] = A[M,256] * B[256,N] ----------------
// LAYER==2 fuses A := relu(A + bias). Double-buffered smem, pad-8 (conflict-free
// fragment loads), warp tile 32x64 = 2x8 m16n8k8 tf32 MMAs.
__device__ __forceinline__ unsigned f2tf(float f) {
    unsigned r;
    asm("cvt.rna.tf32.f32 %0, %1;" : "=r"(r) : "f"(f));
    return r;
}
__device__ __forceinline__ void mma_tf32(float* c, unsigned a0, unsigned a1,
                                         unsigned a2, unsigned a3,
                                         unsigned b0, unsigned b1) {
    asm volatile(
        "mma.sync.aligned.m16n8k8.row.col.f32.tf32.tf32.f32 "
        "{%0,%1,%2,%3}, {%4,%5,%6,%7}, {%8,%9}, {%0,%1,%2,%3};\n"
        : "+f"(c[0]), "+f"(c[1]), "+f"(c[2]), "+f"(c[3])
        : "r"(a0), "r"(a1), "r"(a2), "r"(a3), "r"(b0), "r"(b1));
}

template <int LAYER>
__global__ void __launch_bounds__(256, 2)
gemm_kernel(const float* __restrict__ Ain,
            const float* __restrict__ B,
            const float* __restrict__ bias) {
    constexpr int K = 256;
    constexpr int BK = 16;
    constexpr int NT = K / BK;
    constexpr int N = (LAYER == 1) ? C1 : C2;
    constexpr bool FUSE = (LAYER == 2);
    constexpr int LDS_PAD = 136;   // 128 + 8: conflict-free fragment banks
    const float* A = (LAYER == 1) ? Ain : g_out1;
    float*       C = (LAYER == 1) ? g_h1 : g_h2;
    const int M = NN;

    __shared__ float As[2][BK][LDS_PAD];  // As[k][m]
    __shared__ float Bs[2][BK][LDS_PAD];  // Bs[k][n]

    int tid = threadIdx.x;
    int m0 = blockIdx.y * 128;
    int n0 = blockIdx.x * 128;
    int wid = tid >> 5, lane = tid & 31;
    int warpM = wid & 3;          // m offset 32*warpM
    int warpN = wid >> 2;         // n offset 64*warpN

    // loaders (same pattern as verified fp32 kernel)
    int arow = tid >> 2;          // 0..63
    int acol = (tid & 3) * 4;     // 0,4,8,12
    int brow = tid >> 5;          // 0..7
    int bcol = (tid & 31) * 4;

    int gr0 = m0 + arow, gr1 = m0 + arow + 64;
    const float* Ar0 = A + (size_t)gr0 * K + acol;
    const float* Ar1 = A + (size_t)gr1 * K + acol;

    float acc[2][8][4];
#pragma unroll
    for (int mt = 0; mt < 2; mt++)
#pragma unroll
        for (int nt = 0; nt < 8; nt++)
#pragma unroll
            for (int q = 0; q < 4; q++) acc[mt][nt][q] = 0.f;

    float4 sa0, sa1, sb0, sb1;
    auto fetch = [&](int k0) {
        sa0 = make_float4(0.f, 0.f, 0.f, 0.f);
        sa1 = make_float4(0.f, 0.f, 0.f, 0.f);
        if (gr0 < M) sa0 = *(const float4*)(Ar0 + k0);
        if (gr1 < M) sa1 = *(const float4*)(Ar1 + k0);
        if (FUSE) {
            float4 bv = *(const float4*)(bias + k0 + acol);
            sa0.x = fmaxf(sa0.x + bv.x, 0.f); sa0.y = fmaxf(sa0.y + bv.y, 0.f);
            sa0.z = fmaxf(sa0.z + bv.z, 0.f); sa0.w = fmaxf(sa0.w + bv.w, 0.f);
            sa1.x = fmaxf(sa1.x + bv.x, 0.f); sa1.y = fmaxf(sa1.y + bv.y, 0.f);
            sa1.z = fmaxf(sa1.z + bv.z, 0.f); sa1.w = fmaxf(sa1.w + bv.w, 0.f);
        }
        sb0 = *(const float4*)(B + (size_t)(k0 + brow) * N + n0 + bcol);
        sb1 = *(const float4*)(B + (size_t)(k0 + brow + 8) * N + n0 + bcol);
    };
    auto stage = [&](int buf) {
        As[buf][acol + 0][arow] = sa0.x;
        As[buf][acol + 1][arow] = sa0.y;
        As[buf][acol + 2][arow] = sa0.z;
        As[buf][acol + 3][arow] = sa0.w;
        As[buf][acol + 0][arow + 64] = sa1.x;
        As[buf][acol + 1][arow + 64] = sa1.y;
        As[buf][acol + 2][arow + 64] = sa1.z;
        As[buf][acol + 3][arow + 64] = sa1.w;
        *(float4*)&Bs[buf][brow][bcol] = sb0;
        *(float4*)&Bs[buf][brow + 8][bcol] = sb1;
    };

    fetch(0);
    stage(0);
    __syncthreads();

    int fr = lane >> 2, fc = lane & 3;   // fragment row/col ids
    for (int t = 0; t < NT; t++) {
        int buf = t & 1;
        if (t + 1 < NT) fetch((t + 1) * BK);
#pragma unroll
        for (int kk = 0; kk < BK; kk += 8) {
            // B fragments (8 n-tiles)
            unsigned bf[8][2];
#pragma unroll
            for (int nt = 0; nt < 8; nt++) {
                int nb = 64 * warpN + 8 * nt + fr;
                bf[nt][0] = f2tf(Bs[buf][kk + fc][nb]);
                bf[nt][1] = f2tf(Bs[buf][kk + fc + 4][nb]);
            }
#pragma unroll
            for (int mt = 0; mt < 2; mt++) {
                int mb = 32 * warpM + 16 * mt;
                unsigned a0 = f2tf(As[buf][kk + fc][mb + fr]);
                unsigned a1 = f2tf(As[buf][kk + fc][mb + fr + 8]);
                unsigned a2 = f2tf(As[buf][kk + fc + 4][mb + fr]);
                unsigned a3 = f2tf(As[buf][kk + fc + 4][mb + fr + 8]);
#pragma unroll
                for (int nt = 0; nt < 8; nt++)
                    mma_tf32(acc[mt][nt], a0, a1, a2, a3, bf[nt][0], bf[nt][1]);
            }
        }
        if (t + 1 < NT) {
            stage(buf ^ 1);
            __syncthreads();
        }
    }

    // epilogue: c0/c1 at (row, 2fc), c2/c3 at (row+8, 2fc)
#pragma unroll
    for (int mt = 0; mt < 2; mt++) {
        int row = m0 + 32 * warpM + 16 * mt + fr;
#pragma unroll
        for (int nt = 0; nt < 8; nt++) {
            int col = n0 + 64 * warpN + 8 * nt + 2 * fc;
            if (row < M)
                *(float2*)(C + (size_t)row * N + col) =
                    make_float2(acc[mt][nt][0], acc[mt][nt][1]);
            if (row + 8 < M)
                *(float2*)(C + (size_t)(row + 8) * N + col) =
                    make_float2(acc[mt][nt][2], acc[mt][nt][3]);
        }
    }
}

// ---------------- attention dot products ----------------
__global__ void dots1_kernel(const float* __restrict__ att_src,
                             const float* __restrict__ att_dst) {
    int n = blockIdx.x;
    int c = threadIdx.x;  // 256 threads
    float v = g_h1[n * C1 + c];
    float s = v * att_src[c];
    float d = v * att_dst[c];
#pragma unroll
    for (int o = 16; o > 0; o >>= 1) {
        s += __shfl_xor_sync(0xFFFFFFFFu, s, o);
        d += __shfl_xor_sync(0xFFFFFFFFu, d, o);
    }
    __shared__ float ss[8], sd[8];
    int w = c >> 5;
    if ((c & 31) == 0) { ss[w] = s; sd[w] = d; }
    __syncthreads();
    if (c < NH) {
        g_asrc1[n * NH + c] = ss[2 * c] + ss[2 * c + 1];
        g_adst1[n * NH + c] = sd[2 * c] + sd[2 * c + 1];
    }
}

__global__ void dots2_kernel(const float* __restrict__ att_src,
                             const float* __restrict__ att_dst) {
    int n = blockIdx.x;
    int c = threadIdx.x;  // 128 threads
    float v = g_h2[n * C2 + c];
    float s = v * att_src[c];
    float d = v * att_dst[c];
#pragma unroll
    for (int o = 16; o > 0; o >>= 1) {
        s += __shfl_xor_sync(0xFFFFFFFFu, s, o);
        d += __shfl_xor_sync(0xFFFFFFFFu, d, o);
    }
    __shared__ float ss[4], sd[4];
    if ((c & 31) == 0) { ss[c >> 5] = s; sd[c >> 5] = d; }
    __syncthreads();
    if (c == 0) {
        g_asrc2[n] = ss[0] + ss[1] + ss[2] + ss[3];
        g_adst2[n] = sd[0] + sd[1] + sd[2] + sd[3];
    }
}

// ---------------- fused attention + aggregation (one warp per dst node) ----------------
__device__ __forceinline__ float lrelu(float a) {
    return (a > 0.f) ? a : NEG_SLOPE * a;
}

__global__ void __launch_bounds__(256) agg1_kernel() {
    __shared__ float cache[8][NH * CAP];
    int wid = threadIdx.x >> 5, lane = threadIdx.x & 31;
    int n = blockIdx.x * 8 + wid;
    if (n >= NN) return;
    float* ch = cache[wid];
    int beg = g_off[n], end = g_off[n + 1];
    int deg = end - beg;
    float4 ad = *(const float4*)(g_adst1 + n * 4);

    float mx0 = -CUDART_INF_F, mx1 = -CUDART_INF_F, mx2 = -CUDART_INF_F, mx3 = -CUDART_INF_F;
    for (int i = lane; i < deg; i += 32) {
        int s = g_csr_src[beg + i];
        float4 as = *(const float4*)(g_asrc1 + s * 4);
        float a0 = lrelu(as.x + ad.x), a1 = lrelu(as.y + ad.y);
        float a2 = lrelu(as.z + ad.z), a3 = lrelu(as.w + ad.w);
        if (i < CAP) {
            ch[0 * CAP + i] = a0; ch[1 * CAP + i] = a1;
            ch[2 * CAP + i] = a2; ch[3 * CAP + i] = a3;
        }
        mx0 = fmaxf(mx0, a0); mx1 = fmaxf(mx1, a1);
        mx2 = fmaxf(mx2, a2); mx3 = fmaxf(mx3, a3);
    }
#pragma unroll
    for (int o = 16; o > 0; o >>= 1) {
        mx0 = fmaxf(mx0, __shfl_xor_sync(0xFFFFFFFFu, mx0, o));
        mx1 = fmaxf(mx1, __shfl_xor_sync(0xFFFFFFFFu, mx1, o));
        mx2 = fmaxf(mx2, __shfl_xor_sync(0xFFFFFFFFu, mx2, o));
        mx3 = fmaxf(mx3, __shfl_xor_sync(0xFFFFFFFFu, mx3, o));
    }
    __syncwarp();

    float d0 = 0.f, d1 = 0.f, d2 = 0.f, d3 = 0.f;
    for (int i = lane; i < deg; i += 32) {
        float a0, a1, a2, a3;
        if (i < CAP) {
            a0 = ch[0 * CAP + i]; a1 = ch[1 * CAP + i];
            a2 = ch[2 * CAP + i]; a3 = ch[3 * CAP + i];
        } else {
            int s = g_csr_src[beg + i];
            float4 as = *(const float4*)(g_asrc1 + s * 4);
            a0 = lrelu(as.x + ad.x); a1 = lrelu(as.y + ad.y);
            a2 = lrelu(as.z + ad.z); a3 = lrelu(as.w + ad.w);
        }
        float e0 = expf(a0 - mx0), e1 = expf(a1 - mx1);
        float e2 = expf(a2 - mx2), e3 = expf(a3 - mx3);
        if (i < CAP) {
            ch[0 * CAP + i] = e0; ch[1 * CAP + i] = e1;
            ch[2 * CAP + i] = e2; ch[3 * CAP + i] = e3;
        }
        d0 += e0; d1 += e1; d2 += e2; d3 += e3;
    }
#pragma unroll
    for (int o = 16; o > 0; o >>= 1) {
        d0 += __shfl_xor_sync(0xFFFFFFFFu, d0, o);
        d1 += __shfl_xor_sync(0xFFFFFFFFu, d1, o);
        d2 += __shfl_xor_sync(0xFFFFFFFFu, d2, o);
        d3 += __shfl_xor_sync(0xFFFFFFFFu, d3, o);
    }
    float r0 = 1.f / (d0 + SM_EPS), r1 = 1.f / (d1 + SM_EPS);
    float r2 = 1.f / (d2 + SM_EPS), r3 = 1.f / (d3 + SM_EPS);
    __syncwarp();

    float acc[8];
#pragma unroll
    for (int j = 0; j < 8; j++) acc[j] = 0.f;
    for (int i = 0; i < deg; i++) {
        float w0, w1, w2, w3;
        if (i < CAP) {
            w0 = ch[0 * CAP + i] * r0; w1 = ch[1 * CAP + i] * r1;
            w2 = ch[2 * CAP + i] * r2; w3 = ch[3 * CAP + i] * r3;
        } else {
            int s = g_csr_src[beg + i];
            float4 as = *(const float4*)(g_asrc1 + s * 4);
            w0 = expf(lrelu(as.x + ad.x) - mx0) * r0;
            w1 = expf(lrelu(as.y + ad.y) - mx1) * r1;
            w2 = expf(lrelu(as.z + ad.z) - mx2) * r2;
            w3 = expf(lrelu(as.w + ad.w) - mx3) * r3;
        }
        int s = g_csr_src[beg + i];
        const float* hr = g_h1 + (size_t)s * C1;
        acc[0] += hr[0 * 32 + lane] * w0;
        acc[1] += hr[1 * 32 + lane] * w0;
        acc[2] += hr[2 * 32 + lane] * w1;
        acc[3] += hr[3 * 32 + lane] * w1;
        acc[4] += hr[4 * 32 + lane] * w2;
        acc[5] += hr[5 * 32 + lane] * w2;
        acc[6] += hr[6 * 32 + lane] * w3;
        acc[7] += hr[7 * 32 + lane] * w3;
    }
    float* orow = g_out1 + (size_t)n * C1;
#pragma unroll
    for (int j = 0; j < 8; j++) orow[j * 32 + lane] = acc[j];
}

__global__ void __launch_bounds__(256) agg2_kernel() {
    __shared__ float cache[8][CAP];
    int wid = threadIdx.x >> 5, lane = threadIdx.x & 31;
    int n = blockIdx.x * 8 + wid;
    if (n >= NN) return;
    float* ch = cache[wid];
    int beg = g_off[n], end = g_off[n + 1];
    int deg = end - beg;
    float ad = g_adst2[n];

    float mx = -CUDART_INF_F;
    for (int i = lane; i < deg; i += 32) {
        float a = lrelu(g_asrc2[g_csr_src[beg + i]] + ad);
        if (i < CAP) ch[i] = a;
        mx = fmaxf(mx, a);
    }
#pragma unroll
    for (int o = 16; o > 0; o >>= 1)
        mx = fmaxf(mx, __shfl_xor_sync(0xFFFFFFFFu, mx, o));
    __syncwarp();

    float den = 0.f;
    for (int i = lane; i < deg; i += 32) {
        float a = (i < CAP) ? ch[i]
                            : lrelu(g_asrc2[g_csr_src[beg + i]] + ad);
        float e = expf(a - mx);
        if (i < CAP) ch[i] = e;
        den += e;
    }
#pragma unroll
    for (int o = 16; o > 0; o >>= 1)
        den += __shfl_xor_sync(0xFFFFFFFFu, den, o);
    float rden = 1.f / (den + SM_EPS);
    __syncwarp();

    float acc[4];
#pragma unroll
    for (int j = 0; j < 4; j++) acc[j] = 0.f;
    for (int i = 0; i < deg; i++) {
        int s = g_csr_src[beg + i];
        float w;
        if (i < CAP) w = ch[i] * rden;
        else w = expf(lrelu(g_asrc2[s] + ad) - mx) * rden;
        const float* hr = g_h2 + (size_t)s * C2;
        acc[0] += hr[0 * 32 + lane] * w;
        acc[1] += hr[1 * 32 + lane] * w;
        acc[2] += hr[2 * 32 + lane] * w;
        acc[3] += hr[3 * 32 + lane] * w;
    }
    float* orow = g_out2 + (size_t)n * C2;
#pragma unroll
    for (int j = 0; j < 4; j++) orow[j * 32 + lane] = acc[j];
}

// ---------------- pooling (batch sorted: register-accumulate, flush on change) ----
__global__ void pool_kernel(const float* __restrict__ bias2,
                            float* __restrict__ out) {
    int c = threadIdx.x;            // 128 channels
    int n0 = blockIdx.x * 128;
    int nend = min(n0 + 128, NN);
    float bval = bias2[c];
    float acc = 0.f;
    int cur = g_batch32[n0];
    for (int n = n0; n < nend; n++) {
        int b = g_batch32[n];
        if (b != cur) {
            atomicAdd(out + cur * C2 + c, acc);
            acc = 0.f; cur = b;
        }
        acc += fmaxf(g_out2[(size_t)n * C2 + c] + bval, 0.f);
    }
    atomicAdd(out + cur * C2 + c, acc);
}

__global__ void final_kernel(float* __restrict__ out) {
    int i = blockIdx.x * blockDim.x + threadIdx.x;
    if (i < NG * C2) out[i] /= fmaxf((float)g_cnt[i >> 7], 1.f);
}

// ---------------- host launcher ----------------
extern "C" void kernel_launch(void* const* d_in, const int* in_sizes, int n_in,
                              void* d_out, int out_size) {
    const void *x = 0, *W1 = 0, *W2 = 0, *ei = 0, *batch = 0;
    const void *t256[3] = {0, 0, 0};
    const void *t128[3] = {0, 0, 0};
    int n256 = 0, n128 = 0;
    for (int i = 0; i < n_in; i++) {
        int sz = in_sizes[i];
        if      (sz == NN * CIN)  x = d_in[i];
        else if (sz == CIN * C1)  W1 = d_in[i];
        else if (sz == C1 * C2)   W2 = d_in[i];
        else if (sz == 2 * NE)    ei = d_in[i];
        else if (sz == NN)        batch = d_in[i];
        else if (sz == 256 && n256 < 3) t256[n256++] = d_in[i];
        else if (sz == 128 && n128 < 3) t128[n128++] = d_in[i];
    }
    const float* as1 = (const float*)t256[0];
    const float* ad1 = (const float*)t256[1];
    const float* b1  = (const float*)t256[2];
    const float* as2 = (const float*)t128[0];
    const float* ad2 = (const float*)t128[1];
    const float* b2  = (const float*)t128[2];
    float* out = (float*)d_out;

    // setup
    zdeg_kernel<<<(NN + 255) / 256, 256>>>();
    probe_kernel<<<1, 256>>>(ei, batch);
    convert_kernel<<<(ET + 255) / 256, 256>>>(ei, batch, out);
    scanA_kernel<<<SBLK, 256>>>();
    scanB_kernel<<<1, 64>>>();
    scanC_kernel<<<(NN + 255) / 256, 256>>>();
    scatter_kernel<<<(ET + 255) / 256, 256>>>();

    // layer 1
    gemm_kernel<1><<<dim3(C1 / 128, (NN + 127) / 128), 256>>>((const float*)x, (const float*)W1, nullptr);
    dots1_kernel<<<NN, 256>>>(as1, ad1);
    agg1_kernel<<<(NN + 7) / 8, 256>>>();

    // layer 2 (relu(out1 + b1) fused into GEMM2 A-load)
    gemm_kernel<2><<<dim3(C2 / 128, (NN + 127) / 128), 256>>>(nullptr, (const float*)W2, b1);
    dots2_kernel<<<NN, 128>>>(as2, ad2);
    agg2_kernel<<<(NN + 7) / 8, 256>>>();

    // mean pool
    pool_kernel<<<(NN + 127) / 128, 128>>>(b2, out);
    final_kernel<<<(NG * C2 + 255) / 256, 256>>>(out);
}